// round 12
// baseline (speedup 1.0000x reference)
#include <cuda_runtime.h>
#include <cuda_fp16.h>
#include <mma.h>
#include <cstdint>

using namespace nvcuda;

// Problem constants (fixed by dataset)
#define Nn 50000
#define Dd 128
#define Rr 3
#define Ee 800000
#define OUTD 64
#define ALPHAc 0.5f
#define BETA1c 0.6931471805599453f   // ln 2
#define BETA2c 0.4054651081081644f   // ln 1.5
#define SLOPEc 0.01f

// ---------------- scratch (device globals; no allocations allowed) ----------
__device__ __align__(256) __half g_xs  [(size_t)Rr * Nn * Dd];        // prescaled x (dinv_out)
__device__ __align__(256) __half g_aggh[((size_t)Rr * Nn + 64) * Dd]; // layer-1 operand, padded
__device__ __align__(256) __half g_xh  [((size_t)Nn + 64) * Dd];      // plain fp16 x, padded
__device__ __align__(256) __half g_z   [(size_t)Rr * Nn * OUTD];      // z_r = (h1*d_out_r) @ G_r
__device__ __align__(256) __half g_W1h [Rr * Dd * Dd];                // b1*W1 + (1-b1)*I
__device__ __align__(256) __half g_Gh  [Rr * Dd * OUTD];
__device__ __align__(256) __half g_Gxh [Dd * OUTD];
__device__ int   g_deg_out[Rr * Nn];
__device__ int   g_deg_in[Rr * Nn];
__device__ float g_dinv_out[Rr * Nn];
__device__ float g_dinv_in[Rr * Nn];
__device__ int   g_rowstart[Rr * Nn];
__device__ int   g_fillcur[Rr * Nn];
__device__ int   g_col[(size_t)Rr * Ee];
__device__ int   g_cursor[Rr];
__device__ float g_G[Rr * Dd * OUTD];
__device__ float g_c[OUTD];

// ---------------- init small state -------------------------------------------
__global__ void k_init() {
    int i = blockIdx.x * blockDim.x + threadIdx.x;
    if (i < Rr * Nn) { g_deg_out[i] = 0; g_deg_in[i] = 0; }
    if (i < Rr) g_cursor[i] = 0;
}

// ---------------- launch A: degree histogram + prep1 + prepw1 -----------------
#define DEG_BLOCKS  ((Rr * Ee + 255) / 256)                  // 9375
#define P1_BLOCKS   ((Rr * Dd * OUTD + 255) / 256)           // 96
#define PW1_BLOCKS  ((Rr * Dd * Dd + 255) / 256)             // 192
__global__ void k_degree_prep(const int* __restrict__ src, const int* __restrict__ dst,
                              const float* __restrict__ W2, const float* __restrict__ Wlin,
                              const float* __restrict__ W1) {
    int b = blockIdx.x;
    int t = threadIdx.x;
    if (b < DEG_BLOCKS) {
        int i = b * 256 + t;
        if (i >= Rr * Ee) return;
        int r = i / Ee;
        atomicAdd(&g_deg_out[r * Nn + src[i]], 1);
        atomicAdd(&g_deg_in [r * Nn + dst[i]], 1);
    } else if (b < DEG_BLOCKS + P1_BLOCKS) {
        int idx = (b - DEG_BLOCKS) * 256 + t;
        if (idx >= Rr * Dd * OUTD) return;
        int r = idx / (Dd * OUTD);
        int rem = idx % (Dd * OUTD);
        int i = rem / OUTD, j = rem % OUTD;
        const float* wrow = W2 + ((size_t)r * Dd + i) * Dd;
        float s = 0.f;
#pragma unroll 8
        for (int k = 0; k < Dd; ++k) s += wrow[k] * Wlin[k * OUTD + j];
        g_G[idx] = BETA2c * s + (1.f - BETA2c) * Wlin[rem];
    } else {
        int idx = (b - DEG_BLOCKS - P1_BLOCKS) * 256 + t;
        if (idx >= Rr * Dd * Dd) return;
        int ij = idx % (Dd * Dd);
        int i = ij >> 7, j = ij & 127;
        float v = BETA1c * W1[idx] + ((i == j) ? (1.f - BETA1c) : 0.f);
        g_W1h[idx] = __float2half(v);
    }
}

// ---------------- launch B: row starts + dinv + prep2 --------------------------
#define RS_XBLOCKS ((Nn + 255) / 256)                        // 196
#define RS_BLOCKS  (RS_XBLOCKS * Rr)                         // 588
#define P2_BLOCKS  ((Dd * OUTD + 255) / 256)                 // 32
__global__ void k_rowstart_prep(const float* __restrict__ b2, const float* __restrict__ Wlin,
                                const float* __restrict__ blin) {
    int b = blockIdx.x;
    int t = threadIdx.x;
    if (b < RS_BLOCKS) {
        int r = b / RS_XBLOCKS;
        int n = (b % RS_XBLOCKS) * 256 + t;
        int lane = t & 31;
        int d = (n < Nn) ? g_deg_in[r * Nn + n] : 0;
        int incl = d;
#pragma unroll
        for (int o = 1; o < 32; o <<= 1) {
            int v = __shfl_up_sync(0xffffffffu, incl, o);
            if (lane >= o) incl += v;
        }
        int total = __shfl_sync(0xffffffffu, incl, 31);
        int base = 0;
        if (lane == 31) base = atomicAdd(&g_cursor[r], total);
        base = __shfl_sync(0xffffffffu, base, 31);
        if (n < Nn) {
            int start = r * Ee + base + incl - d;
            g_rowstart[r * Nn + n] = start;
            g_fillcur [r * Nn + n] = start;
            int di = d < 1 ? 1 : d;
            g_dinv_in[r * Nn + n] = rsqrtf((float)di);
            int doo = g_deg_out[r * Nn + n]; if (doo < 1) doo = 1;
            g_dinv_out[r * Nn + n] = rsqrtf((float)doo);
        }
    } else {
        int idx = (b - RS_BLOCKS) * 256 + t;
        if (idx < Dd * OUTD) {
            float v0 = g_G[idx], v1 = g_G[Dd * OUTD + idx], v2 = g_G[2 * Dd * OUTD + idx];
            g_Gxh[idx] = __float2half((ALPHAc / 3.f) * (v0 + v1 + v2));
            const float sc = (1.f - ALPHAc) / 3.f;
            g_Gh[idx]                 = __float2half(v0 * sc);
            g_Gh[Dd * OUTD + idx]     = __float2half(v1 * sc);
            g_Gh[2 * Dd * OUTD + idx] = __float2half(v2 * sc);
        }
        if (idx < OUTD) {
            float cc = blin[idx];
            for (int k = 0; k < Dd; ++k)
                cc += (b2[k] + b2[Dd + k] + b2[2 * Dd + k]) * (1.f / 3.f) * Wlin[k * OUTD + idx];
            g_c[idx] = cc;
        }
    }
}

// ---------------- fp16 helpers --------------------------------------------------
__device__ __forceinline__ void acc_h4(float4& acc, uint2 u) {
    __half2 a = *reinterpret_cast<__half2*>(&u.x);
    __half2 b = *reinterpret_cast<__half2*>(&u.y);
    float2 fa = __half22float2(a), fb = __half22float2(b);
    acc.x += fa.x; acc.y += fa.y; acc.z += fb.x; acc.w += fb.y;
}

// pack 8 floats (scaled) -> 8 halfs (16B)
__device__ __forceinline__ uint4 pack_half8s(const float* v, float s) {
    __half2 p0 = __floats2half2_rn(v[0] * s, v[1] * s);
    __half2 p1 = __floats2half2_rn(v[2] * s, v[3] * s);
    __half2 p2 = __floats2half2_rn(v[4] * s, v[5] * s);
    __half2 p3 = __floats2half2_rn(v[6] * s, v[7] * s);
    uint4 u;
    u.x = *reinterpret_cast<unsigned*>(&p0);
    u.y = *reinterpret_cast<unsigned*>(&p1);
    u.z = *reinterpret_cast<unsigned*>(&p2);
    u.w = *reinterpret_cast<unsigned*>(&p3);
    return u;
}

// ---------------- launch C: CSR fill + prescale + (out = x@Gx + c) -------------
#define CF_BLOCKS  ((Rr * Ee + 255) / 256)                   // 9375
#define PS_BLOCKS  ((Nn * (Dd / 4) + 255) / 256)             // 6250
#define XG_BLOCKS  ((Nn + 63) / 64)                          // 782
__global__ void k_csrfill_prescale(const int* __restrict__ src, const int* __restrict__ dst,
                                   const float* __restrict__ x, float* __restrict__ out) {
    __shared__ __align__(16) unsigned char sm[64 * 136 * 2];   // 17408 B (Ah/Cs union)
    int b = blockIdx.x;
    int t = threadIdx.x;
    if (b < CF_BLOCKS) {
        int i = b * 256 + t;
        if (i >= Rr * Ee) return;
        int r = i / Ee;
        int pos = atomicAdd(&g_fillcur[r * Nn + dst[i]], 1);
        g_col[pos] = src[i];
    } else if (b < CF_BLOCKS + PS_BLOCKS) {
        int i = (b - CF_BLOCKS) * 256 + t;
        if (i >= Nn * (Dd / 4)) return;
        int c4 = i & 31;
        int n = i >> 5;
        float4 v = __ldg(reinterpret_cast<const float4*>(x + (size_t)n * Dd) + c4);
        __half2 q0 = __floats2half2_rn(v.x, v.y);
        __half2 q1 = __floats2half2_rn(v.z, v.w);
        uint2 w;
        w.x = *reinterpret_cast<unsigned*>(&q0);
        w.y = *reinterpret_cast<unsigned*>(&q1);
        *reinterpret_cast<uint2*>(g_xh + (size_t)n * Dd + c4 * 4) = w;
#pragma unroll
        for (int r = 0; r < Rr; ++r) {
            float s = __ldg(g_dinv_out + r * Nn + n);
            __half2 p0 = __floats2half2_rn(v.x * s, v.y * s);
            __half2 p1 = __floats2half2_rn(v.z * s, v.w * s);
            uint2 u;
            u.x = *reinterpret_cast<unsigned*>(&p0);
            u.y = *reinterpret_cast<unsigned*>(&p1);
            *reinterpret_cast<uint2*>(g_xs + ((size_t)r * Nn + n) * Dd + c4 * 4) = u;
        }
    } else {
        // out = x @ Gx + c  (base for the relation reds)
        __half* Ah = reinterpret_cast<__half*>(sm);   // 64x128, stride 136
        float*  Cs = reinterpret_cast<float*>(sm);    // 64x68 after Ah is dead
        int n0 = (b - CF_BLOCKS - PS_BLOCKS) << 6;
        int warp = t >> 5;
        int wr = warp >> 1, wc = warp & 1;
#pragma unroll
        for (int it = 0; it < 8; ++it) {
            int idx = it * 256 + t;              // 2048
            int row = idx >> 5, c4 = idx & 31;
            int n = n0 + row;
            float4 v = (n < Nn)
                ? __ldg(reinterpret_cast<const float4*>(x + (size_t)n * Dd) + c4)
                : make_float4(0.f, 0.f, 0.f, 0.f);
            __half2 p0 = __floats2half2_rn(v.x, v.y);
            __half2 p1 = __floats2half2_rn(v.z, v.w);
            uint2 u;
            u.x = *reinterpret_cast<unsigned*>(&p0);
            u.y = *reinterpret_cast<unsigned*>(&p1);
            *reinterpret_cast<uint2*>(Ah + row * 136 + c4 * 4) = u;
        }
        __syncthreads();
        wmma::fragment<wmma::accumulator, 16, 16, 16, float> acc[2];
#pragma unroll
        for (int f = 0; f < 2; ++f) wmma::fill_fragment(acc[f], 0.f);
#pragma unroll
        for (int k = 0; k < 8; ++k) {
            wmma::fragment<wmma::matrix_a, 16, 16, 16, __half, wmma::row_major> af;
            wmma::load_matrix_sync(af, Ah + (wr * 16) * 136 + k * 16, 136);
#pragma unroll
            for (int f = 0; f < 2; ++f) {
                wmma::fragment<wmma::matrix_b, 16, 16, 16, __half, wmma::row_major> bf;
                wmma::load_matrix_sync(bf, g_Gxh + (k * 16) * OUTD + wc * 32 + f * 16, OUTD);
                wmma::mma_sync(acc[f], af, bf, acc[f]);
            }
        }
        __syncthreads();   // Ah dead before Cs overwrite
#pragma unroll
        for (int f = 0; f < 2; ++f)
            wmma::store_matrix_sync(Cs + (wr * 16) * 68 + wc * 32 + f * 16, acc[f], 68,
                                    wmma::mem_row_major);
        __syncthreads();
#pragma unroll
        for (int it = 0; it < 8; ++it) {
            int idx = it * 256 + t;
            int row = idx >> 5, cp = idx & 31;
            int n = n0 + row;
            if (n < Nn) {
                float2 p;
                p.x = Cs[row * 68 + cp * 2]     + g_c[cp * 2];
                p.y = Cs[row * 68 + cp * 2 + 1] + g_c[cp * 2 + 1];
                *(reinterpret_cast<float2*>(out + (size_t)n * OUTD) + cp) = p;
            }
        }
    }
}

// ---------------- gather (layer 1): aggh = (1-a)*dinv_in*sum + a*x -------------
__launch_bounds__(256)
__global__ void k_gather1() {
    int gw = (blockIdx.x * blockDim.x + threadIdx.x) >> 5;   // (r,n) index
    if (gw >= Rr * Nn) return;
    int lane = threadIdx.x & 31;
    int n = gw % Nn;
    const __half* base = g_xs + (size_t)(gw / Nn) * Nn * Dd;

    int beg = __ldg(g_rowstart + gw);
    int end = beg + __ldg(g_deg_in + gw);
    float4 acc = make_float4(0.f, 0.f, 0.f, 0.f);
    int e = beg;
#pragma unroll 1
    for (; e + 4 <= end; e += 4) {
        int s0 = __ldg(g_col + e);
        int s1 = __ldg(g_col + e + 1);
        int s2 = __ldg(g_col + e + 2);
        int s3 = __ldg(g_col + e + 3);
        uint2 u0 = __ldg(reinterpret_cast<const uint2*>(base + (size_t)s0 * Dd) + lane);
        uint2 u1 = __ldg(reinterpret_cast<const uint2*>(base + (size_t)s1 * Dd) + lane);
        uint2 u2 = __ldg(reinterpret_cast<const uint2*>(base + (size_t)s2 * Dd) + lane);
        uint2 u3 = __ldg(reinterpret_cast<const uint2*>(base + (size_t)s3 * Dd) + lane);
        acc_h4(acc, u0); acc_h4(acc, u1); acc_h4(acc, u2); acc_h4(acc, u3);
    }
#pragma unroll 1
    for (; e < end; ++e) {
        int s0 = __ldg(g_col + e);
        uint2 u0 = __ldg(reinterpret_cast<const uint2*>(base + (size_t)s0 * Dd) + lane);
        acc_h4(acc, u0);
    }
    float sc = __ldg(g_dinv_in + gw) * (1.f - ALPHAc);
    uint2 xv = __ldg(reinterpret_cast<const uint2*>(g_xh + (size_t)n * Dd) + lane);
    float4 xf = make_float4(0.f, 0.f, 0.f, 0.f);
    acc_h4(xf, xv);
    float4 o;
    o.x = acc.x * sc + ALPHAc * xf.x;
    o.y = acc.y * sc + ALPHAc * xf.y;
    o.z = acc.z * sc + ALPHAc * xf.z;
    o.w = acc.w * sc + ALPHAc * xf.w;
    __half2 p0 = __floats2half2_rn(o.x, o.y);
    __half2 p1 = __floats2half2_rn(o.z, o.w);
    uint2 u;
    u.x = *reinterpret_cast<unsigned*>(&p0);
    u.y = *reinterpret_cast<unsigned*>(&p1);
    *reinterpret_cast<uint2*>(g_aggh + (size_t)gw * Dd + lane * 4) = u;
}

// copy a 64x128 fp16 tile global -> smem (stride 136), coalesced uint4
__device__ __forceinline__ void stage_tile(__half* Ah, const __half* __restrict__ Ab,
                                           int tid) {
#pragma unroll
    for (int it = 0; it < 4; ++it) {
        int idx = it * 256 + tid;            // 1024 uint4 total
        int row = idx >> 4, c8 = idx & 15;
        uint4 u = __ldg(reinterpret_cast<const uint4*>(Ab + (size_t)row * Dd) + c8);
        *reinterpret_cast<uint4*>(Ah + row * 136 + c8 * 8) = u;
    }
}

// ---------------- layer-1 GEMM + fused z-projection ---------------------------
// C = aggh_r @ W1'_r ; epi: +bias, leaky, 1/3 mean -> hacc (h1 tile in regs)
// then for each r: z_r = (h1 * dinv_out_r) @ G_r  (wmma from smem, no h1 spill)
__launch_bounds__(256)
__global__ void k_gemm1(const float* __restrict__ b1) {
    __shared__ __align__(16) __half Ah[64 * 136];   // 17408 B
    __shared__ __align__(16) float  Cs[64 * 132];   // 33792 B
    int tid = threadIdx.x;
    int warp = tid >> 5;
    int ty = tid >> 4, tx = tid & 15;
    int wr = warp >> 1, wc = warp & 1;
    int n0 = blockIdx.x << 6;

    float hacc[4][8];
#pragma unroll
    for (int i = 0; i < 4; ++i)
#pragma unroll
        for (int j = 0; j < 8; ++j) hacc[i][j] = 0.f;

    // ---- phase 1: h1 tile via 3 relation GEMMs
    for (int r = 0; r < Rr; ++r) {
        if (r > 0) __syncthreads();
        stage_tile(Ah, g_aggh + ((size_t)r * Nn + n0) * Dd, tid);
        __syncthreads();

        wmma::fragment<wmma::accumulator, 16, 16, 16, float> acc[4];
#pragma unroll
        for (int f = 0; f < 4; ++f) wmma::fill_fragment(acc[f], 0.f);
        const __half* Bg = g_W1h + (size_t)r * Dd * Dd;
#pragma unroll
        for (int k = 0; k < 8; ++k) {
            wmma::fragment<wmma::matrix_a, 16, 16, 16, __half, wmma::row_major> af;
            wmma::load_matrix_sync(af, Ah + (wr * 16) * 136 + k * 16, 136);
#pragma unroll
            for (int f = 0; f < 4; ++f) {
                wmma::fragment<wmma::matrix_b, 16, 16, 16, __half, wmma::row_major> bf;
                wmma::load_matrix_sync(bf, Bg + (k * 16) * Dd + wc * 64 + f * 16, Dd);
                wmma::mma_sync(acc[f], af, bf, acc[f]);
            }
        }
#pragma unroll
        for (int f = 0; f < 4; ++f)
            wmma::store_matrix_sync(Cs + (wr * 16) * 132 + wc * 64 + f * 16, acc[f], 132,
                                    wmma::mem_row_major);
        __syncthreads();

#pragma unroll
        for (int i = 0; i < 4; ++i) {
            int row = ty * 4 + i;
#pragma unroll
            for (int j = 0; j < 8; ++j) {
                int col = tx * 8 + j;
                float v = Cs[row * 132 + col] + b1[r * Dd + col];
                v = v >= 0.f ? v : SLOPEc * v;
                hacc[i][j] += v * (1.f / 3.f);
            }
        }
    }

    // ---- phase 2: z_r = (h1 * dinv_out_r) @ G_r, straight from registers
    for (int r = 0; r < Rr; ++r) {
        __syncthreads();   // previous phase's smem reads complete
#pragma unroll
        for (int i = 0; i < 4; ++i) {
            int row = ty * 4 + i;
            int n = n0 + row;
            float s = (n < Nn) ? __ldg(g_dinv_out + r * Nn + n) : 0.f;
            uint4 u = pack_half8s(hacc[i], s);
            *reinterpret_cast<uint4*>(Ah + row * 136 + tx * 8) = u;
        }
        __syncthreads();

        wmma::fragment<wmma::accumulator, 16, 16, 16, float> acc2[2];
#pragma unroll
        for (int f = 0; f < 2; ++f) wmma::fill_fragment(acc2[f], 0.f);
        const __half* Bb = g_Gh + (size_t)r * Dd * OUTD;
#pragma unroll
        for (int k = 0; k < 8; ++k) {
            wmma::fragment<wmma::matrix_a, 16, 16, 16, __half, wmma::row_major> af;
            wmma::load_matrix_sync(af, Ah + (wr * 16) * 136 + k * 16, 136);
#pragma unroll
            for (int f = 0; f < 2; ++f) {
                wmma::fragment<wmma::matrix_b, 16, 16, 16, __half, wmma::row_major> bf;
                wmma::load_matrix_sync(bf, Bb + (k * 16) * OUTD + wc * 32 + f * 16, OUTD);
                wmma::mma_sync(acc2[f], af, bf, acc2[f]);
            }
        }
        // Cs does not alias Ah — safe to store without an extra barrier
#pragma unroll
        for (int f = 0; f < 2; ++f)
            wmma::store_matrix_sync(Cs + (wr * 16) * 68 + wc * 32 + f * 16, acc2[f], 68,
                                    wmma::mem_row_major);
        __syncthreads();

#pragma unroll
        for (int it = 0; it < 8; ++it) {
            int idx = it * 256 + tid;        // 2048
            int row = idx >> 5, cp = idx & 31;
            int n = n0 + row;
            if (n < Nn) {
                __half2 p = __floats2half2_rn(Cs[row * 68 + cp * 2], Cs[row * 68 + cp * 2 + 1]);
                *(reinterpret_cast<unsigned*>(g_z + ((size_t)r * Nn + n) * OUTD) + cp) =
                    *reinterpret_cast<unsigned*>(&p);
            }
        }
    }
}

// ---------------- combine: one warp per (r,n); red.v2 into out -----------------
__launch_bounds__(256)
__global__ void k_combine(float* __restrict__ out) {
    int gw = (blockIdx.x * blockDim.x + threadIdx.x) >> 5;   // (r,n)
    if (gw >= Rr * Nn) return;
    int lane = threadIdx.x & 31;
    int n = gw % Nn;
    const __half* zb = g_z + (size_t)(gw / Nn) * Nn * OUTD;

    int beg = __ldg(g_rowstart + gw);
    int end = beg + __ldg(g_deg_in + gw);
    float2 acc = make_float2(0.f, 0.f);
    int e = beg;
#pragma unroll 1
    for (; e + 4 <= end; e += 4) {
        int s0 = __ldg(g_col + e);
        int s1 = __ldg(g_col + e + 1);
        int s2 = __ldg(g_col + e + 2);
        int s3 = __ldg(g_col + e + 3);
        unsigned u0 = __ldg(reinterpret_cast<const unsigned*>(zb + (size_t)s0 * OUTD) + lane);
        unsigned u1 = __ldg(reinterpret_cast<const unsigned*>(zb + (size_t)s1 * OUTD) + lane);
        unsigned u2 = __ldg(reinterpret_cast<const unsigned*>(zb + (size_t)s2 * OUTD) + lane);
        unsigned u3 = __ldg(reinterpret_cast<const unsigned*>(zb + (size_t)s3 * OUTD) + lane);
        float2 f0 = __half22float2(*reinterpret_cast<__half2*>(&u0));
        float2 f1 = __half22float2(*reinterpret_cast<__half2*>(&u1));
        float2 f2 = __half22float2(*reinterpret_cast<__half2*>(&u2));
        float2 f3 = __half22float2(*reinterpret_cast<__half2*>(&u3));
        acc.x += f0.x + f1.x + f2.x + f3.x;
        acc.y += f0.y + f1.y + f2.y + f3.y;
    }
#pragma unroll 1
    for (; e < end; ++e) {
        int s0 = __ldg(g_col + e);
        unsigned u0 = __ldg(reinterpret_cast<const unsigned*>(zb + (size_t)s0 * OUTD) + lane);
        float2 f0 = __half22float2(*reinterpret_cast<__half2*>(&u0));
        acc.x += f0.x; acc.y += f0.y;
    }
    float di = __ldg(g_dinv_in + gw);
    float vx = acc.x * di, vy = acc.y * di;
    float* p = out + (size_t)n * OUTD + lane * 2;
    asm volatile("red.global.add.v2.f32 [%0], {%1,%2};"
                 :: "l"(p), "f"(vx), "f"(vy) : "memory");
}

// ---------------- launch ------------------------------------------------------
extern "C" void kernel_launch(void* const* d_in, const int* in_sizes, int n_in,
                              void* d_out, int out_size) {
    const float* x    = (const float*)d_in[0];
    const int*   src  = (const int*)  d_in[1];
    const int*   dst  = (const int*)  d_in[2];
    const float* W1   = (const float*)d_in[3];
    const float* b1   = (const float*)d_in[4];
    const float* W2   = (const float*)d_in[5];
    const float* b2   = (const float*)d_in[6];
    const float* Wlin = (const float*)d_in[7];
    const float* blin = (const float*)d_in[8];
    float* out = (float*)d_out;

    k_init<<<(Rr * Nn + 255) / 256, 256>>>();
    k_degree_prep<<<DEG_BLOCKS + P1_BLOCKS + PW1_BLOCKS, 256>>>(src, dst, W2, Wlin, W1);
    k_rowstart_prep<<<RS_BLOCKS + P2_BLOCKS, 256>>>(b2, Wlin, blin);
    k_csrfill_prescale<<<CF_BLOCKS + PS_BLOCKS + XG_BLOCKS, 256>>>(src, dst, x, out);

    const int gather_blocks = (Rr * Nn * 32 + 255) / 256;   // one warp per (r,n)
    k_gather1<<<gather_blocks, 256>>>();
    k_gemm1<<<(Nn + 63) / 64, 256>>>(b1);
    k_combine<<<gather_blocks, 256>>>(out);
}

// round 13
// speedup vs baseline: 1.0683x; 1.0683x over previous
#include <cuda_runtime.h>
#include <cuda_fp16.h>
#include <mma.h>
#include <cstdint>

using namespace nvcuda;

// Problem constants (fixed by dataset)
#define Nn 50000
#define Dd 128
#define Rr 3
#define Ee 800000
#define OUTD 64
#define ALPHAc 0.5f
#define BETA1c 0.6931471805599453f   // ln 2
#define BETA2c 0.4054651081081644f   // ln 1.5
#define SLOPEc 0.01f

// ---------------- scratch (device globals; no allocations allowed) ----------
__device__ __align__(256) __half g_xs  [(size_t)Rr * Nn * Dd];        // prescaled x (dinv_out)
__device__ __align__(256) __half g_aggh[((size_t)Rr * Nn + 64) * Dd]; // layer-1 operand, padded
__device__ __align__(256) __half g_xh  [((size_t)Nn + 64) * Dd];      // plain fp16 x, padded
__device__ __align__(256) __half g_z   [(size_t)Rr * Nn * OUTD];      // z_r = (h1*d_out_r) @ G_r
__device__ __align__(256) __half g_W1h [Rr * Dd * Dd];                // b1*W1 + (1-b1)*I
__device__ __align__(256) __half g_Gh  [Rr * Dd * OUTD];
__device__ __align__(256) __half g_Gxh [Dd * OUTD];
__device__ int   g_deg_out[Rr * Nn];
__device__ int   g_deg_in[Rr * Nn];
__device__ float g_dinv_out[Rr * Nn];
__device__ float g_dinv_in[Rr * Nn];
__device__ int   g_rowstart[Rr * Nn];
__device__ int   g_fillcur[Rr * Nn];
__device__ int   g_col[(size_t)Rr * Ee];
__device__ int   g_cursor[Rr];
__device__ float g_G[Rr * Dd * OUTD];
__device__ float g_c[OUTD];

// ---------------- init small state -------------------------------------------
__global__ void k_init() {
    int i = blockIdx.x * blockDim.x + threadIdx.x;
    if (i < Rr * Nn) { g_deg_out[i] = 0; g_deg_in[i] = 0; }
    if (i < Rr) g_cursor[i] = 0;
}

// ---------------- launch A: degree histogram + prep1 + prepw1 -----------------
#define DEG_BLOCKS  ((Rr * Ee + 255) / 256)                  // 9375
#define P1_BLOCKS   ((Rr * Dd * OUTD + 255) / 256)           // 96
#define PW1_BLOCKS  ((Rr * Dd * Dd + 255) / 256)             // 192
__global__ void k_degree_prep(const int* __restrict__ src, const int* __restrict__ dst,
                              const float* __restrict__ W2, const float* __restrict__ Wlin,
                              const float* __restrict__ W1) {
    int b = blockIdx.x;
    int t = threadIdx.x;
    if (b < DEG_BLOCKS) {
        int i = b * 256 + t;
        if (i >= Rr * Ee) return;
        int r = i / Ee;
        atomicAdd(&g_deg_out[r * Nn + src[i]], 1);
        atomicAdd(&g_deg_in [r * Nn + dst[i]], 1);
    } else if (b < DEG_BLOCKS + P1_BLOCKS) {
        int idx = (b - DEG_BLOCKS) * 256 + t;
        if (idx >= Rr * Dd * OUTD) return;
        int r = idx / (Dd * OUTD);
        int rem = idx % (Dd * OUTD);
        int i = rem / OUTD, j = rem % OUTD;
        const float* wrow = W2 + ((size_t)r * Dd + i) * Dd;
        float s = 0.f;
#pragma unroll 8
        for (int k = 0; k < Dd; ++k) s += wrow[k] * Wlin[k * OUTD + j];
        g_G[idx] = BETA2c * s + (1.f - BETA2c) * Wlin[rem];
    } else {
        int idx = (b - DEG_BLOCKS - P1_BLOCKS) * 256 + t;
        if (idx >= Rr * Dd * Dd) return;
        int ij = idx % (Dd * Dd);
        int i = ij >> 7, j = ij & 127;
        float v = BETA1c * W1[idx] + ((i == j) ? (1.f - BETA1c) : 0.f);
        g_W1h[idx] = __float2half(v);
    }
}

// ---------------- launch B: row starts + dinv + prep2 --------------------------
#define RS_XBLOCKS ((Nn + 255) / 256)                        // 196
#define RS_BLOCKS  (RS_XBLOCKS * Rr)                         // 588
#define P2_BLOCKS  ((Dd * OUTD + 255) / 256)                 // 32
__global__ void k_rowstart_prep(const float* __restrict__ b2, const float* __restrict__ Wlin,
                                const float* __restrict__ blin) {
    int b = blockIdx.x;
    int t = threadIdx.x;
    if (b < RS_BLOCKS) {
        int r = b / RS_XBLOCKS;
        int n = (b % RS_XBLOCKS) * 256 + t;
        int lane = t & 31;
        int d = (n < Nn) ? g_deg_in[r * Nn + n] : 0;
        int incl = d;
#pragma unroll
        for (int o = 1; o < 32; o <<= 1) {
            int v = __shfl_up_sync(0xffffffffu, incl, o);
            if (lane >= o) incl += v;
        }
        int total = __shfl_sync(0xffffffffu, incl, 31);
        int base = 0;
        if (lane == 31) base = atomicAdd(&g_cursor[r], total);
        base = __shfl_sync(0xffffffffu, base, 31);
        if (n < Nn) {
            int start = r * Ee + base + incl - d;
            g_rowstart[r * Nn + n] = start;
            g_fillcur [r * Nn + n] = start;
            int di = d < 1 ? 1 : d;
            g_dinv_in[r * Nn + n] = rsqrtf((float)di);
            int doo = g_deg_out[r * Nn + n]; if (doo < 1) doo = 1;
            g_dinv_out[r * Nn + n] = rsqrtf((float)doo);
        }
    } else {
        int idx = (b - RS_BLOCKS) * 256 + t;
        if (idx < Dd * OUTD) {
            float v0 = g_G[idx], v1 = g_G[Dd * OUTD + idx], v2 = g_G[2 * Dd * OUTD + idx];
            g_Gxh[idx] = __float2half((ALPHAc / 3.f) * (v0 + v1 + v2));
            const float sc = (1.f - ALPHAc) / 3.f;
            g_Gh[idx]                 = __float2half(v0 * sc);
            g_Gh[Dd * OUTD + idx]     = __float2half(v1 * sc);
            g_Gh[2 * Dd * OUTD + idx] = __float2half(v2 * sc);
        }
        if (idx < OUTD) {
            float cc = blin[idx];
            for (int k = 0; k < Dd; ++k)
                cc += (b2[k] + b2[Dd + k] + b2[2 * Dd + k]) * (1.f / 3.f) * Wlin[k * OUTD + idx];
            g_c[idx] = cc;
        }
    }
}

// ---------------- launch C: CSR fill + prescale (lightweight, no smem) --------
#define CF_BLOCKS  ((Rr * Ee + 255) / 256)                   // 9375
#define PS_BLOCKS  ((Nn * (Dd / 4) + 255) / 256)             // 6250
__global__ void k_csrfill_prescale(const int* __restrict__ src, const int* __restrict__ dst,
                                   const float* __restrict__ x) {
    int b = blockIdx.x;
    int t = threadIdx.x;
    if (b < CF_BLOCKS) {
        int i = b * 256 + t;
        if (i >= Rr * Ee) return;
        int r = i / Ee;
        int pos = atomicAdd(&g_fillcur[r * Nn + dst[i]], 1);
        g_col[pos] = src[i];
    } else {
        int i = (b - CF_BLOCKS) * 256 + t;
        if (i >= Nn * (Dd / 4)) return;
        int c4 = i & 31;
        int n = i >> 5;
        float4 v = __ldg(reinterpret_cast<const float4*>(x + (size_t)n * Dd) + c4);
        __half2 q0 = __floats2half2_rn(v.x, v.y);
        __half2 q1 = __floats2half2_rn(v.z, v.w);
        uint2 w;
        w.x = *reinterpret_cast<unsigned*>(&q0);
        w.y = *reinterpret_cast<unsigned*>(&q1);
        *reinterpret_cast<uint2*>(g_xh + (size_t)n * Dd + c4 * 4) = w;
#pragma unroll
        for (int r = 0; r < Rr; ++r) {
            float s = __ldg(g_dinv_out + r * Nn + n);
            __half2 p0 = __floats2half2_rn(v.x * s, v.y * s);
            __half2 p1 = __floats2half2_rn(v.z * s, v.w * s);
            uint2 u;
            u.x = *reinterpret_cast<unsigned*>(&p0);
            u.y = *reinterpret_cast<unsigned*>(&p1);
            *reinterpret_cast<uint2*>(g_xs + ((size_t)r * Nn + n) * Dd + c4 * 4) = u;
        }
    }
}

// ---------------- fp16 helpers --------------------------------------------------
__device__ __forceinline__ void acc_h4(float4& acc, uint2 u) {
    __half2 a = *reinterpret_cast<__half2*>(&u.x);
    __half2 b = *reinterpret_cast<__half2*>(&u.y);
    float2 fa = __half22float2(a), fb = __half22float2(b);
    acc.x += fa.x; acc.y += fa.y; acc.z += fb.x; acc.w += fb.y;
}

// pack 8 floats (scaled) -> 8 halfs (16B)
__device__ __forceinline__ uint4 pack_half8s(const float* v, float s) {
    __half2 p0 = __floats2half2_rn(v[0] * s, v[1] * s);
    __half2 p1 = __floats2half2_rn(v[2] * s, v[3] * s);
    __half2 p2 = __floats2half2_rn(v[4] * s, v[5] * s);
    __half2 p3 = __floats2half2_rn(v[6] * s, v[7] * s);
    uint4 u;
    u.x = *reinterpret_cast<unsigned*>(&p0);
    u.y = *reinterpret_cast<unsigned*>(&p1);
    u.z = *reinterpret_cast<unsigned*>(&p2);
    u.w = *reinterpret_cast<unsigned*>(&p3);
    return u;
}

// ---------------- gather (layer 1): aggh = (1-a)*dinv_in*sum + a*x -------------
__launch_bounds__(256)
__global__ void k_gather1() {
    int gw = (blockIdx.x * blockDim.x + threadIdx.x) >> 5;   // (r,n) index
    if (gw >= Rr * Nn) return;
    int lane = threadIdx.x & 31;
    int n = gw % Nn;
    const __half* base = g_xs + (size_t)(gw / Nn) * Nn * Dd;

    int beg = __ldg(g_rowstart + gw);
    int end = beg + __ldg(g_deg_in + gw);
    float4 acc = make_float4(0.f, 0.f, 0.f, 0.f);
    int e = beg;
#pragma unroll 1
    for (; e + 4 <= end; e += 4) {
        int s0 = __ldg(g_col + e);
        int s1 = __ldg(g_col + e + 1);
        int s2 = __ldg(g_col + e + 2);
        int s3 = __ldg(g_col + e + 3);
        uint2 u0 = __ldg(reinterpret_cast<const uint2*>(base + (size_t)s0 * Dd) + lane);
        uint2 u1 = __ldg(reinterpret_cast<const uint2*>(base + (size_t)s1 * Dd) + lane);
        uint2 u2 = __ldg(reinterpret_cast<const uint2*>(base + (size_t)s2 * Dd) + lane);
        uint2 u3 = __ldg(reinterpret_cast<const uint2*>(base + (size_t)s3 * Dd) + lane);
        acc_h4(acc, u0); acc_h4(acc, u1); acc_h4(acc, u2); acc_h4(acc, u3);
    }
#pragma unroll 1
    for (; e < end; ++e) {
        int s0 = __ldg(g_col + e);
        uint2 u0 = __ldg(reinterpret_cast<const uint2*>(base + (size_t)s0 * Dd) + lane);
        acc_h4(acc, u0);
    }
    float sc = __ldg(g_dinv_in + gw) * (1.f - ALPHAc);
    uint2 xv = __ldg(reinterpret_cast<const uint2*>(g_xh + (size_t)n * Dd) + lane);
    float4 xf = make_float4(0.f, 0.f, 0.f, 0.f);
    acc_h4(xf, xv);
    float4 o;
    o.x = acc.x * sc + ALPHAc * xf.x;
    o.y = acc.y * sc + ALPHAc * xf.y;
    o.z = acc.z * sc + ALPHAc * xf.z;
    o.w = acc.w * sc + ALPHAc * xf.w;
    __half2 p0 = __floats2half2_rn(o.x, o.y);
    __half2 p1 = __floats2half2_rn(o.z, o.w);
    uint2 u;
    u.x = *reinterpret_cast<unsigned*>(&p0);
    u.y = *reinterpret_cast<unsigned*>(&p1);
    *reinterpret_cast<uint2*>(g_aggh + (size_t)gw * Dd + lane * 4) = u;
}

// copy a 64x128 fp16 tile global -> smem (stride 136), coalesced uint4
__device__ __forceinline__ void stage_tile(__half* Ah, const __half* __restrict__ Ab,
                                           int tid) {
#pragma unroll
    for (int it = 0; it < 4; ++it) {
        int idx = it * 256 + tid;            // 1024 uint4 total
        int row = idx >> 4, c8 = idx & 15;
        uint4 u = __ldg(reinterpret_cast<const uint4*>(Ab + (size_t)row * Dd) + c8);
        *reinterpret_cast<uint4*>(Ah + row * 136 + c8 * 8) = u;
    }
}

// ---------------- layer-1 GEMM + fused z-projection + x@Gx slice --------------
// blocks [0, GB1): h1 tile + z_r projection (heavy path)
// blocks [GB1, GB1+XG): out = x@Gx + c (light path, same launch)
#define GB1_BLOCKS ((Nn + 63) / 64)                          // 782
#define XG_BLOCKS  ((Nn + 63) / 64)                          // 782
__launch_bounds__(256)
__global__ void k_gemm1(const float* __restrict__ b1, const float* __restrict__ x,
                        float* __restrict__ out) {
    __shared__ __align__(16) __half Ah[64 * 136];   // 17408 B
    __shared__ __align__(16) float  Cs[64 * 132];   // 33792 B
    int tid = threadIdx.x;
    int warp = tid >> 5;
    int ty = tid >> 4, tx = tid & 15;
    int wr = warp >> 1, wc = warp & 1;

    if (blockIdx.x >= GB1_BLOCKS) {
        // ---- light path: out = x @ Gx + c
        int n0 = (blockIdx.x - GB1_BLOCKS) << 6;
#pragma unroll
        for (int it = 0; it < 8; ++it) {
            int idx = it * 256 + tid;              // 2048
            int row = idx >> 5, c4 = idx & 31;
            int n = n0 + row;
            float4 v = (n < Nn)
                ? __ldg(reinterpret_cast<const float4*>(x + (size_t)n * Dd) + c4)
                : make_float4(0.f, 0.f, 0.f, 0.f);
            __half2 p0 = __floats2half2_rn(v.x, v.y);
            __half2 p1 = __floats2half2_rn(v.z, v.w);
            uint2 u;
            u.x = *reinterpret_cast<unsigned*>(&p0);
            u.y = *reinterpret_cast<unsigned*>(&p1);
            *reinterpret_cast<uint2*>(Ah + row * 136 + c4 * 4) = u;
        }
        __syncthreads();
        wmma::fragment<wmma::accumulator, 16, 16, 16, float> acc[2];
#pragma unroll
        for (int f = 0; f < 2; ++f) wmma::fill_fragment(acc[f], 0.f);
#pragma unroll
        for (int k = 0; k < 8; ++k) {
            wmma::fragment<wmma::matrix_a, 16, 16, 16, __half, wmma::row_major> af;
            wmma::load_matrix_sync(af, Ah + (wr * 16) * 136 + k * 16, 136);
#pragma unroll
            for (int f = 0; f < 2; ++f) {
                wmma::fragment<wmma::matrix_b, 16, 16, 16, __half, wmma::row_major> bf;
                wmma::load_matrix_sync(bf, g_Gxh + (k * 16) * OUTD + wc * 32 + f * 16, OUTD);
                wmma::mma_sync(acc[f], af, bf, acc[f]);
            }
        }
#pragma unroll
        for (int f = 0; f < 2; ++f)
            wmma::store_matrix_sync(Cs + (wr * 16) * 68 + wc * 32 + f * 16, acc[f], 68,
                                    wmma::mem_row_major);
        __syncthreads();
#pragma unroll
        for (int it = 0; it < 8; ++it) {
            int idx = it * 256 + tid;
            int row = idx >> 5, cp = idx & 31;
            int n = n0 + row;
            if (n < Nn) {
                float2 p;
                p.x = Cs[row * 68 + cp * 2]     + g_c[cp * 2];
                p.y = Cs[row * 68 + cp * 2 + 1] + g_c[cp * 2 + 1];
                *(reinterpret_cast<float2*>(out + (size_t)n * OUTD) + cp) = p;
            }
        }
        return;
    }

    // ---- heavy path: h1 tile via 3 relation GEMMs, then z_r projection
    int n0 = blockIdx.x << 6;
    float hacc[4][8];
#pragma unroll
    for (int i = 0; i < 4; ++i)
#pragma unroll
        for (int j = 0; j < 8; ++j) hacc[i][j] = 0.f;

    for (int r = 0; r < Rr; ++r) {
        if (r > 0) __syncthreads();
        stage_tile(Ah, g_aggh + ((size_t)r * Nn + n0) * Dd, tid);
        __syncthreads();

        wmma::fragment<wmma::accumulator, 16, 16, 16, float> acc[4];
#pragma unroll
        for (int f = 0; f < 4; ++f) wmma::fill_fragment(acc[f], 0.f);
        const __half* Bg = g_W1h + (size_t)r * Dd * Dd;
#pragma unroll
        for (int k = 0; k < 8; ++k) {
            wmma::fragment<wmma::matrix_a, 16, 16, 16, __half, wmma::row_major> af;
            wmma::load_matrix_sync(af, Ah + (wr * 16) * 136 + k * 16, 136);
#pragma unroll
            for (int f = 0; f < 4; ++f) {
                wmma::fragment<wmma::matrix_b, 16, 16, 16, __half, wmma::row_major> bf;
                wmma::load_matrix_sync(bf, Bg + (k * 16) * Dd + wc * 64 + f * 16, Dd);
                wmma::mma_sync(acc[f], af, bf, acc[f]);
            }
        }
#pragma unroll
        for (int f = 0; f < 4; ++f)
            wmma::store_matrix_sync(Cs + (wr * 16) * 132 + wc * 64 + f * 16, acc[f], 132,
                                    wmma::mem_row_major);
        __syncthreads();

#pragma unroll
        for (int i = 0; i < 4; ++i) {
            int row = ty * 4 + i;
#pragma unroll
            for (int j = 0; j < 8; ++j) {
                int col = tx * 8 + j;
                float v = Cs[row * 132 + col] + b1[r * Dd + col];
                v = v >= 0.f ? v : SLOPEc * v;
                hacc[i][j] += v * (1.f / 3.f);
            }
        }
    }

    // z_r = (h1 * dinv_out_r) @ G_r straight from registers
    for (int r = 0; r < Rr; ++r) {
        __syncthreads();
#pragma unroll
        for (int i = 0; i < 4; ++i) {
            int row = ty * 4 + i;
            int n = n0 + row;
            float s = (n < Nn) ? __ldg(g_dinv_out + r * Nn + n) : 0.f;
            uint4 u = pack_half8s(hacc[i], s);
            *reinterpret_cast<uint4*>(Ah + row * 136 + tx * 8) = u;
        }
        __syncthreads();

        wmma::fragment<wmma::accumulator, 16, 16, 16, float> acc2[2];
#pragma unroll
        for (int f = 0; f < 2; ++f) wmma::fill_fragment(acc2[f], 0.f);
        const __half* Bb = g_Gh + (size_t)r * Dd * OUTD;
#pragma unroll
        for (int k = 0; k < 8; ++k) {
            wmma::fragment<wmma::matrix_a, 16, 16, 16, __half, wmma::row_major> af;
            wmma::load_matrix_sync(af, Ah + (wr * 16) * 136 + k * 16, 136);
#pragma unroll
            for (int f = 0; f < 2; ++f) {
                wmma::fragment<wmma::matrix_b, 16, 16, 16, __half, wmma::row_major> bf;
                wmma::load_matrix_sync(bf, Bb + (k * 16) * OUTD + wc * 32 + f * 16, OUTD);
                wmma::mma_sync(acc2[f], af, bf, acc2[f]);
            }
        }
#pragma unroll
        for (int f = 0; f < 2; ++f)
            wmma::store_matrix_sync(Cs + (wr * 16) * 68 + wc * 32 + f * 16, acc2[f], 68,
                                    wmma::mem_row_major);
        __syncthreads();

#pragma unroll
        for (int it = 0; it < 8; ++it) {
            int idx = it * 256 + tid;        // 2048
            int row = idx >> 5, cp = idx & 31;
            int n = n0 + row;
            if (n < Nn) {
                __half2 p = __floats2half2_rn(Cs[row * 68 + cp * 2], Cs[row * 68 + cp * 2 + 1]);
                *(reinterpret_cast<unsigned*>(g_z + ((size_t)r * Nn + n) * OUTD) + cp) =
                    *reinterpret_cast<unsigned*>(&p);
            }
        }
    }
}

// ---------------- combine: one warp per (r,n); red.v2 into out -----------------
__launch_bounds__(256)
__global__ void k_combine(float* __restrict__ out) {
    int gw = (blockIdx.x * blockDim.x + threadIdx.x) >> 5;   // (r,n)
    if (gw >= Rr * Nn) return;
    int lane = threadIdx.x & 31;
    int n = gw % Nn;
    const __half* zb = g_z + (size_t)(gw / Nn) * Nn * OUTD;

    int beg = __ldg(g_rowstart + gw);
    int end = beg + __ldg(g_deg_in + gw);
    float2 acc = make_float2(0.f, 0.f);
    int e = beg;
#pragma unroll 1
    for (; e + 4 <= end; e += 4) {
        int s0 = __ldg(g_col + e);
        int s1 = __ldg(g_col + e + 1);
        int s2 = __ldg(g_col + e + 2);
        int s3 = __ldg(g_col + e + 3);
        unsigned u0 = __ldg(reinterpret_cast<const unsigned*>(zb + (size_t)s0 * OUTD) + lane);
        unsigned u1 = __ldg(reinterpret_cast<const unsigned*>(zb + (size_t)s1 * OUTD) + lane);
        unsigned u2 = __ldg(reinterpret_cast<const unsigned*>(zb + (size_t)s2 * OUTD) + lane);
        unsigned u3 = __ldg(reinterpret_cast<const unsigned*>(zb + (size_t)s3 * OUTD) + lane);
        float2 f0 = __half22float2(*reinterpret_cast<__half2*>(&u0));
        float2 f1 = __half22float2(*reinterpret_cast<__half2*>(&u1));
        float2 f2 = __half22float2(*reinterpret_cast<__half2*>(&u2));
        float2 f3 = __half22float2(*reinterpret_cast<__half2*>(&u3));
        acc.x += f0.x + f1.x + f2.x + f3.x;
        acc.y += f0.y + f1.y + f2.y + f3.y;
    }
#pragma unroll 1
    for (; e < end; ++e) {
        int s0 = __ldg(g_col + e);
        unsigned u0 = __ldg(reinterpret_cast<const unsigned*>(zb + (size_t)s0 * OUTD) + lane);
        float2 f0 = __half22float2(*reinterpret_cast<__half2*>(&u0));
        acc.x += f0.x; acc.y += f0.y;
    }
    float di = __ldg(g_dinv_in + gw);
    float vx = acc.x * di, vy = acc.y * di;
    float* p = out + (size_t)n * OUTD + lane * 2;
    asm volatile("red.global.add.v2.f32 [%0], {%1,%2};"
                 :: "l"(p), "f"(vx), "f"(vy) : "memory");
}

// ---------------- launch ------------------------------------------------------
extern "C" void kernel_launch(void* const* d_in, const int* in_sizes, int n_in,
                              void* d_out, int out_size) {
    const float* x    = (const float*)d_in[0];
    const int*   src  = (const int*)  d_in[1];
    const int*   dst  = (const int*)  d_in[2];
    const float* W1   = (const float*)d_in[3];
    const float* b1   = (const float*)d_in[4];
    const float* W2   = (const float*)d_in[5];
    const float* b2   = (const float*)d_in[6];
    const float* Wlin = (const float*)d_in[7];
    const float* blin = (const float*)d_in[8];
    float* out = (float*)d_out;

    k_init<<<(Rr * Nn + 255) / 256, 256>>>();
    k_degree_prep<<<DEG_BLOCKS + P1_BLOCKS + PW1_BLOCKS, 256>>>(src, dst, W2, Wlin, W1);
    k_rowstart_prep<<<RS_BLOCKS + P2_BLOCKS, 256>>>(b2, Wlin, blin);
    k_csrfill_prescale<<<CF_BLOCKS + PS_BLOCKS, 256>>>(src, dst, x);

    const int gather_blocks = (Rr * Nn * 32 + 255) / 256;   // one warp per (r,n)
    k_gather1<<<gather_blocks, 256>>>();
    k_gemm1<<<GB1_BLOCKS + XG_BLOCKS, 256>>>(b1, x, out);
    k_combine<<<gather_blocks, 256>>>(out);
}

// round 14
// speedup vs baseline: 1.0923x; 1.0225x over previous
#include <cuda_runtime.h>
#include <cuda_fp16.h>
#include <mma.h>
#include <cstdint>

using namespace nvcuda;

// Problem constants (fixed by dataset)
#define Nn 50000
#define Dd 128
#define Rr 3
#define Ee 800000
#define OUTD 64
#define ALPHAc 0.5f
#define BETA1c 0.6931471805599453f   // ln 2
#define BETA2c 0.4054651081081644f   // ln 1.5
#define SLOPEc 0.01f

// ---------------- scratch (device globals; no allocations allowed) ----------
__device__ __align__(256) __half g_xs  [(size_t)Rr * Nn * Dd];        // prescaled x (dinv_out)
__device__ __align__(256) __half g_aggh[((size_t)Rr * Nn + 64) * Dd]; // layer-1 operand, padded
__device__ __align__(256) __half g_xh  [((size_t)Nn + 64) * Dd];      // plain fp16 x, padded
__device__ __align__(256) __half g_z   [(size_t)Rr * Nn * OUTD];      // z_r = (h1*d_out_r) @ G_r
__device__ __align__(256) __half g_W1h [Rr * Dd * Dd];                // b1*W1 + (1-b1)*I
__device__ __align__(256) __half g_Gh  [Rr * Dd * OUTD];
__device__ __align__(256) __half g_Gxh [Dd * OUTD];
__device__ int   g_deg_out[Rr * Nn];
__device__ int   g_deg_in[Rr * Nn];
__device__ float g_dinv_out[Rr * Nn];
__device__ float g_dinv_in[Rr * Nn];
__device__ int   g_rowstart[Rr * Nn];
__device__ int   g_fillcur[Rr * Nn];
__device__ int   g_col[(size_t)Rr * Ee];
__device__ int   g_cursor[Rr];
__device__ float g_G[Rr * Dd * OUTD];
__device__ float g_c[OUTD];

// ---------------- init small state -------------------------------------------
__global__ void k_init() {
    int i = blockIdx.x * blockDim.x + threadIdx.x;
    if (i < Rr * Nn) { g_deg_out[i] = 0; g_deg_in[i] = 0; }
    if (i < Rr) g_cursor[i] = 0;
}

// ---------------- launch A: degree histogram + prep1 + prepw1 -----------------
#define DEG_BLOCKS  ((Rr * Ee + 255) / 256)                  // 9375
#define P1_BLOCKS   ((Rr * Dd * OUTD + 255) / 256)           // 96
#define PW1_BLOCKS  ((Rr * Dd * Dd + 255) / 256)             // 192
__global__ void k_degree_prep(const int* __restrict__ src, const int* __restrict__ dst,
                              const float* __restrict__ W2, const float* __restrict__ Wlin,
                              const float* __restrict__ W1) {
    int b = blockIdx.x;
    int t = threadIdx.x;
    if (b < DEG_BLOCKS) {
        int i = b * 256 + t;
        if (i >= Rr * Ee) return;
        int r = i / Ee;
        atomicAdd(&g_deg_out[r * Nn + src[i]], 1);
        atomicAdd(&g_deg_in [r * Nn + dst[i]], 1);
    } else if (b < DEG_BLOCKS + P1_BLOCKS) {
        int idx = (b - DEG_BLOCKS) * 256 + t;
        if (idx >= Rr * Dd * OUTD) return;
        int r = idx / (Dd * OUTD);
        int rem = idx % (Dd * OUTD);
        int i = rem / OUTD, j = rem % OUTD;
        const float* wrow = W2 + ((size_t)r * Dd + i) * Dd;
        float s = 0.f;
#pragma unroll 8
        for (int k = 0; k < Dd; ++k) s += wrow[k] * Wlin[k * OUTD + j];
        g_G[idx] = BETA2c * s + (1.f - BETA2c) * Wlin[rem];
    } else {
        int idx = (b - DEG_BLOCKS - P1_BLOCKS) * 256 + t;
        if (idx >= Rr * Dd * Dd) return;
        int ij = idx % (Dd * Dd);
        int i = ij >> 7, j = ij & 127;
        float v = BETA1c * W1[idx] + ((i == j) ? (1.f - BETA1c) : 0.f);
        g_W1h[idx] = __float2half(v);
    }
}

// ---------------- launch B: row starts + dinv + prep2 --------------------------
#define RS_XBLOCKS ((Nn + 255) / 256)                        // 196
#define RS_BLOCKS  (RS_XBLOCKS * Rr)                         // 588
#define P2_BLOCKS  ((Dd * OUTD + 255) / 256)                 // 32
__global__ void k_rowstart_prep(const float* __restrict__ b2, const float* __restrict__ Wlin,
                                const float* __restrict__ blin) {
    int b = blockIdx.x;
    int t = threadIdx.x;
    if (b < RS_BLOCKS) {
        int r = b / RS_XBLOCKS;
        int n = (b % RS_XBLOCKS) * 256 + t;
        int lane = t & 31;
        int d = (n < Nn) ? g_deg_in[r * Nn + n] : 0;
        int incl = d;
#pragma unroll
        for (int o = 1; o < 32; o <<= 1) {
            int v = __shfl_up_sync(0xffffffffu, incl, o);
            if (lane >= o) incl += v;
        }
        int total = __shfl_sync(0xffffffffu, incl, 31);
        int base = 0;
        if (lane == 31) base = atomicAdd(&g_cursor[r], total);
        base = __shfl_sync(0xffffffffu, base, 31);
        if (n < Nn) {
            int start = r * Ee + base + incl - d;
            g_rowstart[r * Nn + n] = start;
            g_fillcur [r * Nn + n] = start;
            int di = d < 1 ? 1 : d;
            g_dinv_in[r * Nn + n] = rsqrtf((float)di);
            int doo = g_deg_out[r * Nn + n]; if (doo < 1) doo = 1;
            g_dinv_out[r * Nn + n] = rsqrtf((float)doo);
        }
    } else {
        int idx = (b - RS_BLOCKS) * 256 + t;
        if (idx < Dd * OUTD) {
            float v0 = g_G[idx], v1 = g_G[Dd * OUTD + idx], v2 = g_G[2 * Dd * OUTD + idx];
            g_Gxh[idx] = __float2half((ALPHAc / 3.f) * (v0 + v1 + v2));
            const float sc = (1.f - ALPHAc) / 3.f;
            g_Gh[idx]                 = __float2half(v0 * sc);
            g_Gh[Dd * OUTD + idx]     = __float2half(v1 * sc);
            g_Gh[2 * Dd * OUTD + idx] = __float2half(v2 * sc);
        }
        if (idx < OUTD) {
            float cc = blin[idx];
            for (int k = 0; k < Dd; ++k)
                cc += (b2[k] + b2[Dd + k] + b2[2 * Dd + k]) * (1.f / 3.f) * Wlin[k * OUTD + idx];
            g_c[idx] = cc;
        }
    }
}

// ---------------- launch C: CSR fill + prescale (lightweight, no smem) --------
#define CF_BLOCKS  ((Rr * Ee + 255) / 256)                   // 9375
#define PS_BLOCKS  ((Nn * (Dd / 4) + 255) / 256)             // 6250
__global__ void k_csrfill_prescale(const int* __restrict__ src, const int* __restrict__ dst,
                                   const float* __restrict__ x) {
    int b = blockIdx.x;
    int t = threadIdx.x;
    if (b < CF_BLOCKS) {
        int i = b * 256 + t;
        if (i >= Rr * Ee) return;
        int r = i / Ee;
        int pos = atomicAdd(&g_fillcur[r * Nn + dst[i]], 1);
        g_col[pos] = src[i];
    } else {
        int i = (b - CF_BLOCKS) * 256 + t;
        if (i >= Nn * (Dd / 4)) return;
        int c4 = i & 31;
        int n = i >> 5;
        float4 v = __ldg(reinterpret_cast<const float4*>(x + (size_t)n * Dd) + c4);
        __half2 q0 = __floats2half2_rn(v.x, v.y);
        __half2 q1 = __floats2half2_rn(v.z, v.w);
        uint2 w;
        w.x = *reinterpret_cast<unsigned*>(&q0);
        w.y = *reinterpret_cast<unsigned*>(&q1);
        *reinterpret_cast<uint2*>(g_xh + (size_t)n * Dd + c4 * 4) = w;
#pragma unroll
        for (int r = 0; r < Rr; ++r) {
            float s = __ldg(g_dinv_out + r * Nn + n);
            __half2 p0 = __floats2half2_rn(v.x * s, v.y * s);
            __half2 p1 = __floats2half2_rn(v.z * s, v.w * s);
            uint2 u;
            u.x = *reinterpret_cast<unsigned*>(&p0);
            u.y = *reinterpret_cast<unsigned*>(&p1);
            *reinterpret_cast<uint2*>(g_xs + ((size_t)r * Nn + n) * Dd + c4 * 4) = u;
        }
    }
}

// ---------------- fp16 helpers --------------------------------------------------
__device__ __forceinline__ void acc_h4(float4& acc, uint2 u) {
    __half2 a = *reinterpret_cast<__half2*>(&u.x);
    __half2 b = *reinterpret_cast<__half2*>(&u.y);
    float2 fa = __half22float2(a), fb = __half22float2(b);
    acc.x += fa.x; acc.y += fa.y; acc.z += fb.x; acc.w += fb.y;
}

// accumulate 8 halfs (uint4) into two float4
__device__ __forceinline__ void acc_h8(float4& a0, float4& a1, uint4 u) {
    acc_h4(a0, make_uint2(u.x, u.y));
    acc_h4(a1, make_uint2(u.z, u.w));
}

// pack 8 floats (scaled) -> 8 halfs (16B)
__device__ __forceinline__ uint4 pack_half8s(const float* v, float s) {
    __half2 p0 = __floats2half2_rn(v[0] * s, v[1] * s);
    __half2 p1 = __floats2half2_rn(v[2] * s, v[3] * s);
    __half2 p2 = __floats2half2_rn(v[4] * s, v[5] * s);
    __half2 p3 = __floats2half2_rn(v[6] * s, v[7] * s);
    uint4 u;
    u.x = *reinterpret_cast<unsigned*>(&p0);
    u.y = *reinterpret_cast<unsigned*>(&p1);
    u.z = *reinterpret_cast<unsigned*>(&p2);
    u.w = *reinterpret_cast<unsigned*>(&p3);
    return u;
}

// ---------------- gather (layer 1): half-warp-wide rows, 2 edges per load -----
// aggh = (1-a)*dinv_in*sum + a*x ; 16 lanes x uint4 cover a 256B row
__launch_bounds__(256)
__global__ void k_gather1() {
    int gw = (blockIdx.x * blockDim.x + threadIdx.x) >> 5;   // (r,n) index
    if (gw >= Rr * Nn) return;
    int lane = threadIdx.x & 31;
    int half = lane >> 4;          // 0: edge e, 1: edge e+1
    int sub  = lane & 15;          // halfs [sub*8, sub*8+8)
    int n = gw % Nn;
    const __half* base = g_xs + (size_t)(gw / Nn) * Nn * Dd;

    int beg = __ldg(g_rowstart + gw);
    int end = beg + __ldg(g_deg_in + gw);
    float4 a0 = make_float4(0.f, 0.f, 0.f, 0.f);
    float4 a1 = make_float4(0.f, 0.f, 0.f, 0.f);
    int e = beg;
#pragma unroll 1
    for (; e + 8 <= end; e += 8) {
        int s0 = __ldg(g_col + e + 0 + half);
        int s1 = __ldg(g_col + e + 2 + half);
        int s2 = __ldg(g_col + e + 4 + half);
        int s3 = __ldg(g_col + e + 6 + half);
        uint4 u0 = __ldg(reinterpret_cast<const uint4*>(base + (size_t)s0 * Dd) + sub);
        uint4 u1 = __ldg(reinterpret_cast<const uint4*>(base + (size_t)s1 * Dd) + sub);
        uint4 u2 = __ldg(reinterpret_cast<const uint4*>(base + (size_t)s2 * Dd) + sub);
        uint4 u3 = __ldg(reinterpret_cast<const uint4*>(base + (size_t)s3 * Dd) + sub);
        acc_h8(a0, a1, u0); acc_h8(a0, a1, u1);
        acc_h8(a0, a1, u2); acc_h8(a0, a1, u3);
    }
#pragma unroll 1
    for (; e < end; e += 2) {
        if (e + half < end) {
            int s0 = __ldg(g_col + e + half);
            uint4 u0 = __ldg(reinterpret_cast<const uint4*>(base + (size_t)s0 * Dd) + sub);
            acc_h8(a0, a1, u0);
        }
    }
    // merge the two half-warps (full-warp shfl before any divergence)
    a0.x += __shfl_xor_sync(0xffffffffu, a0.x, 16);
    a0.y += __shfl_xor_sync(0xffffffffu, a0.y, 16);
    a0.z += __shfl_xor_sync(0xffffffffu, a0.z, 16);
    a0.w += __shfl_xor_sync(0xffffffffu, a0.w, 16);
    a1.x += __shfl_xor_sync(0xffffffffu, a1.x, 16);
    a1.y += __shfl_xor_sync(0xffffffffu, a1.y, 16);
    a1.z += __shfl_xor_sync(0xffffffffu, a1.z, 16);
    a1.w += __shfl_xor_sync(0xffffffffu, a1.w, 16);

    if (half == 0) {
        float sc = __ldg(g_dinv_in + gw) * (1.f - ALPHAc);
        uint4 xv = __ldg(reinterpret_cast<const uint4*>(g_xh + (size_t)n * Dd) + sub);
        float4 x0 = make_float4(0.f, 0.f, 0.f, 0.f);
        float4 x1 = make_float4(0.f, 0.f, 0.f, 0.f);
        acc_h8(x0, x1, xv);
        float v[8];
        v[0] = a0.x * sc + ALPHAc * x0.x;
        v[1] = a0.y * sc + ALPHAc * x0.y;
        v[2] = a0.z * sc + ALPHAc * x0.z;
        v[3] = a0.w * sc + ALPHAc * x0.w;
        v[4] = a1.x * sc + ALPHAc * x1.x;
        v[5] = a1.y * sc + ALPHAc * x1.y;
        v[6] = a1.z * sc + ALPHAc * x1.z;
        v[7] = a1.w * sc + ALPHAc * x1.w;
        uint4 u = pack_half8s(v, 1.f);
        *(reinterpret_cast<uint4*>(g_aggh + (size_t)gw * Dd) + sub) = u;
    }
}

// copy a 64x128 fp16 tile global -> smem (stride 136), coalesced uint4
__device__ __forceinline__ void stage_tile(__half* Ah, const __half* __restrict__ Ab,
                                           int tid) {
#pragma unroll
    for (int it = 0; it < 4; ++it) {
        int idx = it * 256 + tid;            // 1024 uint4 total
        int row = idx >> 4, c8 = idx & 15;
        uint4 u = __ldg(reinterpret_cast<const uint4*>(Ab + (size_t)row * Dd) + c8);
        *reinterpret_cast<uint4*>(Ah + row * 136 + c8 * 8) = u;
    }
}

// ---------------- layer-1 GEMM + fused z-projection + x@Gx slice --------------
#define GB1_BLOCKS ((Nn + 63) / 64)                          // 782
#define XG_BLOCKS  ((Nn + 63) / 64)                          // 782
__launch_bounds__(256)
__global__ void k_gemm1(const float* __restrict__ b1, const float* __restrict__ x,
                        float* __restrict__ out) {
    __shared__ __align__(16) __half Ah[64 * 136];   // 17408 B
    __shared__ __align__(16) float  Cs[64 * 132];   // 33792 B
    int tid = threadIdx.x;
    int warp = tid >> 5;
    int ty = tid >> 4, tx = tid & 15;
    int wr = warp >> 1, wc = warp & 1;

    if (blockIdx.x >= GB1_BLOCKS) {
        // ---- light path: out = x @ Gx + c
        int n0 = (blockIdx.x - GB1_BLOCKS) << 6;
#pragma unroll
        for (int it = 0; it < 8; ++it) {
            int idx = it * 256 + tid;              // 2048
            int row = idx >> 5, c4 = idx & 31;
            int n = n0 + row;
            float4 v = (n < Nn)
                ? __ldg(reinterpret_cast<const float4*>(x + (size_t)n * Dd) + c4)
                : make_float4(0.f, 0.f, 0.f, 0.f);
            __half2 p0 = __floats2half2_rn(v.x, v.y);
            __half2 p1 = __floats2half2_rn(v.z, v.w);
            uint2 u;
            u.x = *reinterpret_cast<unsigned*>(&p0);
            u.y = *reinterpret_cast<unsigned*>(&p1);
            *reinterpret_cast<uint2*>(Ah + row * 136 + c4 * 4) = u;
        }
        __syncthreads();
        wmma::fragment<wmma::accumulator, 16, 16, 16, float> acc[2];
#pragma unroll
        for (int f = 0; f < 2; ++f) wmma::fill_fragment(acc[f], 0.f);
#pragma unroll
        for (int k = 0; k < 8; ++k) {
            wmma::fragment<wmma::matrix_a, 16, 16, 16, __half, wmma::row_major> af;
            wmma::load_matrix_sync(af, Ah + (wr * 16) * 136 + k * 16, 136);
#pragma unroll
            for (int f = 0; f < 2; ++f) {
                wmma::fragment<wmma::matrix_b, 16, 16, 16, __half, wmma::row_major> bf;
                wmma::load_matrix_sync(bf, g_Gxh + (k * 16) * OUTD + wc * 32 + f * 16, OUTD);
                wmma::mma_sync(acc[f], af, bf, acc[f]);
            }
        }
#pragma unroll
        for (int f = 0; f < 2; ++f)
            wmma::store_matrix_sync(Cs + (wr * 16) * 68 + wc * 32 + f * 16, acc[f], 68,
                                    wmma::mem_row_major);
        __syncthreads();
#pragma unroll
        for (int it = 0; it < 8; ++it) {
            int idx = it * 256 + tid;
            int row = idx >> 5, cp = idx & 31;
            int n = n0 + row;
            if (n < Nn) {
                float2 p;
                p.x = Cs[row * 68 + cp * 2]     + g_c[cp * 2];
                p.y = Cs[row * 68 + cp * 2 + 1] + g_c[cp * 2 + 1];
                *(reinterpret_cast<float2*>(out + (size_t)n * OUTD) + cp) = p;
            }
        }
        return;
    }

    // ---- heavy path: h1 tile via 3 relation GEMMs, then z_r projection
    int n0 = blockIdx.x << 6;
    float hacc[4][8];
#pragma unroll
    for (int i = 0; i < 4; ++i)
#pragma unroll
        for (int j = 0; j < 8; ++j) hacc[i][j] = 0.f;

    for (int r = 0; r < Rr; ++r) {
        if (r > 0) __syncthreads();
        stage_tile(Ah, g_aggh + ((size_t)r * Nn + n0) * Dd, tid);
        __syncthreads();

        wmma::fragment<wmma::accumulator, 16, 16, 16, float> acc[4];
#pragma unroll
        for (int f = 0; f < 4; ++f) wmma::fill_fragment(acc[f], 0.f);
        const __half* Bg = g_W1h + (size_t)r * Dd * Dd;
#pragma unroll
        for (int k = 0; k < 8; ++k) {
            wmma::fragment<wmma::matrix_a, 16, 16, 16, __half, wmma::row_major> af;
            wmma::load_matrix_sync(af, Ah + (wr * 16) * 136 + k * 16, 136);
#pragma unroll
            for (int f = 0; f < 4; ++f) {
                wmma::fragment<wmma::matrix_b, 16, 16, 16, __half, wmma::row_major> bf;
                wmma::load_matrix_sync(bf, Bg + (k * 16) * Dd + wc * 64 + f * 16, Dd);
                wmma::mma_sync(acc[f], af, bf, acc[f]);
            }
        }
#pragma unroll
        for (int f = 0; f < 4; ++f)
            wmma::store_matrix_sync(Cs + (wr * 16) * 132 + wc * 64 + f * 16, acc[f], 132,
                                    wmma::mem_row_major);
        __syncthreads();

#pragma unroll
        for (int i = 0; i < 4; ++i) {
            int row = ty * 4 + i;
#pragma unroll
            for (int j = 0; j < 8; ++j) {
                int col = tx * 8 + j;
                float v = Cs[row * 132 + col] + b1[r * Dd + col];
                v = v >= 0.f ? v : SLOPEc * v;
                hacc[i][j] += v * (1.f / 3.f);
            }
        }
    }

    // z_r = (h1 * dinv_out_r) @ G_r straight from registers
    for (int r = 0; r < Rr; ++r) {
        __syncthreads();
#pragma unroll
        for (int i = 0; i < 4; ++i) {
            int row = ty * 4 + i;
            int n = n0 + row;
            float s = (n < Nn) ? __ldg(g_dinv_out + r * Nn + n) : 0.f;
            uint4 u = pack_half8s(hacc[i], s);
            *reinterpret_cast<uint4*>(Ah + row * 136 + tx * 8) = u;
        }
        __syncthreads();

        wmma::fragment<wmma::accumulator, 16, 16, 16, float> acc2[2];
#pragma unroll
        for (int f = 0; f < 2; ++f) wmma::fill_fragment(acc2[f], 0.f);
        const __half* Bb = g_Gh + (size_t)r * Dd * OUTD;
#pragma unroll
        for (int k = 0; k < 8; ++k) {
            wmma::fragment<wmma::matrix_a, 16, 16, 16, __half, wmma::row_major> af;
            wmma::load_matrix_sync(af, Ah + (wr * 16) * 136 + k * 16, 136);
#pragma unroll
            for (int f = 0; f < 2; ++f) {
                wmma::fragment<wmma::matrix_b, 16, 16, 16, __half, wmma::row_major> bf;
                wmma::load_matrix_sync(bf, Bb + (k * 16) * OUTD + wc * 32 + f * 16, OUTD);
                wmma::mma_sync(acc2[f], af, bf, acc2[f]);
            }
        }
#pragma unroll
        for (int f = 0; f < 2; ++f)
            wmma::store_matrix_sync(Cs + (wr * 16) * 68 + wc * 32 + f * 16, acc2[f], 68,
                                    wmma::mem_row_major);
        __syncthreads();

#pragma unroll
        for (int it = 0; it < 8; ++it) {
            int idx = it * 256 + tid;        // 2048
            int row = idx >> 5, cp = idx & 31;
            int n = n0 + row;
            if (n < Nn) {
                __half2 p = __floats2half2_rn(Cs[row * 68 + cp * 2], Cs[row * 68 + cp * 2 + 1]);
                *(reinterpret_cast<unsigned*>(g_z + ((size_t)r * Nn + n) * OUTD) + cp) =
                    *reinterpret_cast<unsigned*>(&p);
            }
        }
    }
}

// ---------------- combine: half-warp-wide z rows, red.v4 into out --------------
__launch_bounds__(256)
__global__ void k_combine(float* __restrict__ out) {
    int gw = (blockIdx.x * blockDim.x + threadIdx.x) >> 5;   // (r,n)
    if (gw >= Rr * Nn) return;
    int lane = threadIdx.x & 31;
    int half = lane >> 4;          // 0: edge e, 1: edge e+1
    int sub  = lane & 15;          // cols [sub*4, sub*4+4)
    int n = gw % Nn;
    const __half* zb = g_z + (size_t)(gw / Nn) * Nn * OUTD;

    int beg = __ldg(g_rowstart + gw);
    int end = beg + __ldg(g_deg_in + gw);
    float4 acc = make_float4(0.f, 0.f, 0.f, 0.f);
    int e = beg;
#pragma unroll 1
    for (; e + 8 <= end; e += 8) {
        int s0 = __ldg(g_col + e + 0 + half);
        int s1 = __ldg(g_col + e + 2 + half);
        int s2 = __ldg(g_col + e + 4 + half);
        int s3 = __ldg(g_col + e + 6 + half);
        uint2 u0 = __ldg(reinterpret_cast<const uint2*>(zb + (size_t)s0 * OUTD) + sub);
        uint2 u1 = __ldg(reinterpret_cast<const uint2*>(zb + (size_t)s1 * OUTD) + sub);
        uint2 u2 = __ldg(reinterpret_cast<const uint2*>(zb + (size_t)s2 * OUTD) + sub);
        uint2 u3 = __ldg(reinterpret_cast<const uint2*>(zb + (size_t)s3 * OUTD) + sub);
        acc_h4(acc, u0); acc_h4(acc, u1); acc_h4(acc, u2); acc_h4(acc, u3);
    }
#pragma unroll 1
    for (; e < end; e += 2) {
        if (e + half < end) {
            int s0 = __ldg(g_col + e + half);
            uint2 u0 = __ldg(reinterpret_cast<const uint2*>(zb + (size_t)s0 * OUTD) + sub);
            acc_h4(acc, u0);
        }
    }
    // merge half-warps (full-warp shfl before divergence)
    acc.x += __shfl_xor_sync(0xffffffffu, acc.x, 16);
    acc.y += __shfl_xor_sync(0xffffffffu, acc.y, 16);
    acc.z += __shfl_xor_sync(0xffffffffu, acc.z, 16);
    acc.w += __shfl_xor_sync(0xffffffffu, acc.w, 16);

    if (half == 0) {
        float di = __ldg(g_dinv_in + gw);
        float v0 = acc.x * di, v1 = acc.y * di, v2 = acc.z * di, v3 = acc.w * di;
        float* p = out + (size_t)n * OUTD + sub * 4;
        asm volatile("red.global.add.v4.f32 [%0], {%1,%2,%3,%4};"
                     :: "l"(p), "f"(v0), "f"(v1), "f"(v2), "f"(v3) : "memory");
    }
}

// ---------------- launch ------------------------------------------------------
extern "C" void kernel_launch(void* const* d_in, const int* in_sizes, int n_in,
                              void* d_out, int out_size) {
    const float* x    = (const float*)d_in[0];
    const int*   src  = (const int*)  d_in[1];
    const int*   dst  = (const int*)  d_in[2];
    const float* W1   = (const float*)d_in[3];
    const float* b1   = (const float*)d_in[4];
    const float* W2   = (const float*)d_in[5];
    const float* b2   = (const float*)d_in[6];
    const float* Wlin = (const float*)d_in[7];
    const float* blin = (const float*)d_in[8];
    float* out = (float*)d_out;

    k_init<<<(Rr * Nn + 255) / 256, 256>>>();
    k_degree_prep<<<DEG_BLOCKS + P1_BLOCKS + PW1_BLOCKS, 256>>>(src, dst, W2, Wlin, W1);
    k_rowstart_prep<<<RS_BLOCKS + P2_BLOCKS, 256>>>(b2, Wlin, blin);
    k_csrfill_prescale<<<CF_BLOCKS + PS_BLOCKS, 256>>>(src, dst, x);

    const int gather_blocks = (Rr * Nn * 32 + 255) / 256;   // one warp per (r,n)
    k_gather1<<<gather_blocks, 256>>>();
    k_gemm1<<<GB1_BLOCKS + XG_BLOCKS, 256>>>(b1, x, out);
    k_combine<<<gather_blocks, 256>>>(out);
}

// round 15
// speedup vs baseline: 1.1039x; 1.0106x over previous
#include <cuda_runtime.h>
#include <cuda_fp16.h>
#include <mma.h>
#include <cstdint>

using namespace nvcuda;

// Problem constants (fixed by dataset)
#define Nn 50000
#define Dd 128
#define Rr 3
#define Ee 800000
#define OUTD 64
#define ALPHAc 0.5f
#define BETA1c 0.6931471805599453f   // ln 2
#define BETA2c 0.4054651081081644f   // ln 1.5
#define SLOPEc 0.01f

// ---------------- scratch (device globals; no allocations allowed) ----------
__device__ __align__(256) __half g_aggh[((size_t)Rr * Nn + 64) * Dd]; // layer-1 operand, padded
__device__ __align__(256) __half g_xh  [((size_t)Nn + 64) * Dd];      // plain fp16 x (L2-resident)
__device__ __align__(256) __half g_z   [(size_t)Rr * Nn * OUTD];      // z_r = (h1*d_out_r) @ G_r
__device__ __align__(256) __half g_W1h [Rr * Dd * Dd];                // b1*W1 + (1-b1)*I
__device__ __align__(256) __half g_Gh  [Rr * Dd * OUTD];
__device__ __align__(256) __half g_Gxh [Dd * OUTD];
__device__ int      g_deg_out[Rr * Nn];
__device__ int      g_deg_in[Rr * Nn];
__device__ float    g_dinv_out[Rr * Nn];
__device__ float    g_dinv_in[Rr * Nn];
__device__ int      g_rowstart[Rr * Nn];
__device__ int      g_fillcur[Rr * Nn];
__device__ unsigned g_col[(size_t)Rr * Ee];   // packed: src(16) | fp16 dinv_out(16)
__device__ int      g_cursor[Rr];
__device__ float    g_G[Rr * Dd * OUTD];
__device__ float    g_c[OUTD];

// ---------------- init small state -------------------------------------------
__global__ void k_init() {
    int i = blockIdx.x * blockDim.x + threadIdx.x;
    if (i < Rr * Nn) { g_deg_out[i] = 0; g_deg_in[i] = 0; }
    if (i < Rr) g_cursor[i] = 0;
}

// ---------------- launch A: degree histogram + prep1 + prepw1 -----------------
#define DEG_BLOCKS  ((Rr * Ee + 255) / 256)                  // 9375
#define P1_BLOCKS   ((Rr * Dd * OUTD + 255) / 256)           // 96
#define PW1_BLOCKS  ((Rr * Dd * Dd + 255) / 256)             // 192
__global__ void k_degree_prep(const int* __restrict__ src, const int* __restrict__ dst,
                              const float* __restrict__ W2, const float* __restrict__ Wlin,
                              const float* __restrict__ W1) {
    int b = blockIdx.x;
    int t = threadIdx.x;
    if (b < DEG_BLOCKS) {
        int i = b * 256 + t;
        if (i >= Rr * Ee) return;
        int r = i / Ee;
        atomicAdd(&g_deg_out[r * Nn + src[i]], 1);
        atomicAdd(&g_deg_in [r * Nn + dst[i]], 1);
    } else if (b < DEG_BLOCKS + P1_BLOCKS) {
        int idx = (b - DEG_BLOCKS) * 256 + t;
        if (idx >= Rr * Dd * OUTD) return;
        int r = idx / (Dd * OUTD);
        int rem = idx % (Dd * OUTD);
        int i = rem / OUTD, j = rem % OUTD;
        const float* wrow = W2 + ((size_t)r * Dd + i) * Dd;
        float s = 0.f;
#pragma unroll 8
        for (int k = 0; k < Dd; ++k) s += wrow[k] * Wlin[k * OUTD + j];
        g_G[idx] = BETA2c * s + (1.f - BETA2c) * Wlin[rem];
    } else {
        int idx = (b - DEG_BLOCKS - P1_BLOCKS) * 256 + t;
        if (idx >= Rr * Dd * Dd) return;
        int ij = idx % (Dd * Dd);
        int i = ij >> 7, j = ij & 127;
        float v = BETA1c * W1[idx] + ((i == j) ? (1.f - BETA1c) : 0.f);
        g_W1h[idx] = __float2half(v);
    }
}

// ---------------- launch B: row starts + dinv + prep2 --------------------------
#define RS_XBLOCKS ((Nn + 255) / 256)                        // 196
#define RS_BLOCKS  (RS_XBLOCKS * Rr)                         // 588
#define P2_BLOCKS  ((Dd * OUTD + 255) / 256)                 // 32
__global__ void k_rowstart_prep(const float* __restrict__ b2, const float* __restrict__ Wlin,
                                const float* __restrict__ blin) {
    int b = blockIdx.x;
    int t = threadIdx.x;
    if (b < RS_BLOCKS) {
        int r = b / RS_XBLOCKS;
        int n = (b % RS_XBLOCKS) * 256 + t;
        int lane = t & 31;
        int d = (n < Nn) ? g_deg_in[r * Nn + n] : 0;
        int incl = d;
#pragma unroll
        for (int o = 1; o < 32; o <<= 1) {
            int v = __shfl_up_sync(0xffffffffu, incl, o);
            if (lane >= o) incl += v;
        }
        int total = __shfl_sync(0xffffffffu, incl, 31);
        int base = 0;
        if (lane == 31) base = atomicAdd(&g_cursor[r], total);
        base = __shfl_sync(0xffffffffu, base, 31);
        if (n < Nn) {
            int start = r * Ee + base + incl - d;
            g_rowstart[r * Nn + n] = start;
            g_fillcur [r * Nn + n] = start;
            int di = d < 1 ? 1 : d;
            g_dinv_in[r * Nn + n] = rsqrtf((float)di);
            int doo = g_deg_out[r * Nn + n]; if (doo < 1) doo = 1;
            g_dinv_out[r * Nn + n] = rsqrtf((float)doo);
        }
    } else {
        int idx = (b - RS_BLOCKS) * 256 + t;
        if (idx < Dd * OUTD) {
            float v0 = g_G[idx], v1 = g_G[Dd * OUTD + idx], v2 = g_G[2 * Dd * OUTD + idx];
            g_Gxh[idx] = __float2half((ALPHAc / 3.f) * (v0 + v1 + v2));
            const float sc = (1.f - ALPHAc) / 3.f;
            g_Gh[idx]                 = __float2half(v0 * sc);
            g_Gh[Dd * OUTD + idx]     = __float2half(v1 * sc);
            g_Gh[2 * Dd * OUTD + idx] = __float2half(v2 * sc);
        }
        if (idx < OUTD) {
            float cc = blin[idx];
            for (int k = 0; k < Dd; ++k)
                cc += (b2[k] + b2[Dd + k] + b2[2 * Dd + k]) * (1.f / 3.f) * Wlin[k * OUTD + idx];
            g_c[idx] = cc;
        }
    }
}

// ---------------- launch C: CSR fill (packed scale) + fp16 x -------------------
#define CF_BLOCKS  ((Rr * Ee + 255) / 256)                   // 9375
#define PS_BLOCKS  ((Nn * (Dd / 4) + 255) / 256)             // 6250
__global__ void k_csrfill_prescale(const int* __restrict__ src, const int* __restrict__ dst,
                                   const float* __restrict__ x) {
    int b = blockIdx.x;
    int t = threadIdx.x;
    if (b < CF_BLOCKS) {
        int i = b * 256 + t;
        if (i >= Rr * Ee) return;
        int r = i / Ee;
        int s = src[i];
        __half sh = __float2half(__ldg(g_dinv_out + r * Nn + s));
        unsigned entry = (unsigned)s |
                         ((unsigned)__half_as_ushort(sh) << 16);
        int pos = atomicAdd(&g_fillcur[r * Nn + dst[i]], 1);
        g_col[pos] = entry;
    } else {
        int i = (b - CF_BLOCKS) * 256 + t;
        if (i >= Nn * (Dd / 4)) return;
        int c4 = i & 31;
        int n = i >> 5;
        float4 v = __ldg(reinterpret_cast<const float4*>(x + (size_t)n * Dd) + c4);
        __half2 q0 = __floats2half2_rn(v.x, v.y);
        __half2 q1 = __floats2half2_rn(v.z, v.w);
        uint2 w;
        w.x = *reinterpret_cast<unsigned*>(&q0);
        w.y = *reinterpret_cast<unsigned*>(&q1);
        *reinterpret_cast<uint2*>(g_xh + (size_t)n * Dd + c4 * 4) = w;
    }
}

// ---------------- fp16 helpers --------------------------------------------------
__device__ __forceinline__ void acc_h4(float4& acc, uint2 u) {
    __half2 a = *reinterpret_cast<__half2*>(&u.x);
    __half2 b = *reinterpret_cast<__half2*>(&u.y);
    float2 fa = __half22float2(a), fb = __half22float2(b);
    acc.x += fa.x; acc.y += fa.y; acc.z += fb.x; acc.w += fb.y;
}

// accumulate 8 halfs (uint4), scaled by s, into two float4
__device__ __forceinline__ void acc_h8s(float4& a0, float4& a1, uint4 u, float s) {
    __half2 h0 = *reinterpret_cast<__half2*>(&u.x);
    __half2 h1 = *reinterpret_cast<__half2*>(&u.y);
    __half2 h2 = *reinterpret_cast<__half2*>(&u.z);
    __half2 h3 = *reinterpret_cast<__half2*>(&u.w);
    float2 f0 = __half22float2(h0), f1 = __half22float2(h1);
    float2 f2 = __half22float2(h2), f3 = __half22float2(h3);
    a0.x += s * f0.x; a0.y += s * f0.y; a0.z += s * f1.x; a0.w += s * f1.y;
    a1.x += s * f2.x; a1.y += s * f2.y; a1.z += s * f3.x; a1.w += s * f3.y;
}

// accumulate 8 halfs (uint4, unscaled) into two float4
__device__ __forceinline__ void acc_h8(float4& a0, float4& a1, uint4 u) {
    acc_h4(a0, make_uint2(u.x, u.y));
    acc_h4(a1, make_uint2(u.z, u.w));
}

// pack 8 floats (scaled) -> 8 halfs (16B)
__device__ __forceinline__ uint4 pack_half8s(const float* v, float s) {
    __half2 p0 = __floats2half2_rn(v[0] * s, v[1] * s);
    __half2 p1 = __floats2half2_rn(v[2] * s, v[3] * s);
    __half2 p2 = __floats2half2_rn(v[4] * s, v[5] * s);
    __half2 p3 = __floats2half2_rn(v[6] * s, v[7] * s);
    uint4 u;
    u.x = *reinterpret_cast<unsigned*>(&p0);
    u.y = *reinterpret_cast<unsigned*>(&p1);
    u.z = *reinterpret_cast<unsigned*>(&p2);
    u.w = *reinterpret_cast<unsigned*>(&p3);
    return u;
}

// ---------------- gather (layer 1): packed-scale edges, L2-resident x ----------
// aggh = (1-a)*dinv_in * sum_e(x[src]*dout[src]) + a*x[n]
// half-warp per edge: 16 lanes x uint4 cover a 256B row; scale from entry
__launch_bounds__(256)
__global__ void k_gather1() {
    int gw = (blockIdx.x * blockDim.x + threadIdx.x) >> 5;   // (r,n) index
    if (gw >= Rr * Nn) return;
    int lane = threadIdx.x & 31;
    int half = lane >> 4;          // 0: edge e, 1: edge e+1
    int sub  = lane & 15;          // halfs [sub*8, sub*8+8)
    int n = gw % Nn;

    int beg = __ldg(g_rowstart + gw);
    int end = beg + __ldg(g_deg_in + gw);
    float4 a0 = make_float4(0.f, 0.f, 0.f, 0.f);
    float4 a1 = make_float4(0.f, 0.f, 0.f, 0.f);
    int e = beg;
#pragma unroll 1
    for (; e + 8 <= end; e += 8) {
        unsigned e0 = __ldg(g_col + e + 0 + half);
        unsigned e1 = __ldg(g_col + e + 2 + half);
        unsigned e2 = __ldg(g_col + e + 4 + half);
        unsigned e3 = __ldg(g_col + e + 6 + half);
        uint4 u0 = __ldg(reinterpret_cast<const uint4*>(g_xh + (size_t)(e0 & 0xffffu) * Dd) + sub);
        uint4 u1 = __ldg(reinterpret_cast<const uint4*>(g_xh + (size_t)(e1 & 0xffffu) * Dd) + sub);
        uint4 u2 = __ldg(reinterpret_cast<const uint4*>(g_xh + (size_t)(e2 & 0xffffu) * Dd) + sub);
        uint4 u3 = __ldg(reinterpret_cast<const uint4*>(g_xh + (size_t)(e3 & 0xffffu) * Dd) + sub);
        float s0 = __half2float(__ushort_as_half((unsigned short)(e0 >> 16)));
        float s1 = __half2float(__ushort_as_half((unsigned short)(e1 >> 16)));
        float s2 = __half2float(__ushort_as_half((unsigned short)(e2 >> 16)));
        float s3 = __half2float(__ushort_as_half((unsigned short)(e3 >> 16)));
        acc_h8s(a0, a1, u0, s0); acc_h8s(a0, a1, u1, s1);
        acc_h8s(a0, a1, u2, s2); acc_h8s(a0, a1, u3, s3);
    }
#pragma unroll 1
    for (; e < end; e += 2) {
        if (e + half < end) {
            unsigned e0 = __ldg(g_col + e + half);
            uint4 u0 = __ldg(reinterpret_cast<const uint4*>(g_xh + (size_t)(e0 & 0xffffu) * Dd) + sub);
            float s0 = __half2float(__ushort_as_half((unsigned short)(e0 >> 16)));
            acc_h8s(a0, a1, u0, s0);
        }
    }
    // merge the two half-warps (full-warp shfl before any divergence)
    a0.x += __shfl_xor_sync(0xffffffffu, a0.x, 16);
    a0.y += __shfl_xor_sync(0xffffffffu, a0.y, 16);
    a0.z += __shfl_xor_sync(0xffffffffu, a0.z, 16);
    a0.w += __shfl_xor_sync(0xffffffffu, a0.w, 16);
    a1.x += __shfl_xor_sync(0xffffffffu, a1.x, 16);
    a1.y += __shfl_xor_sync(0xffffffffu, a1.y, 16);
    a1.z += __shfl_xor_sync(0xffffffffu, a1.z, 16);
    a1.w += __shfl_xor_sync(0xffffffffu, a1.w, 16);

    if (half == 0) {
        float sc = __ldg(g_dinv_in + gw) * (1.f - ALPHAc);
        uint4 xv = __ldg(reinterpret_cast<const uint4*>(g_xh + (size_t)n * Dd) + sub);
        float4 x0 = make_float4(0.f, 0.f, 0.f, 0.f);
        float4 x1 = make_float4(0.f, 0.f, 0.f, 0.f);
        acc_h8(x0, x1, xv);
        float v[8];
        v[0] = a0.x * sc + ALPHAc * x0.x;
        v[1] = a0.y * sc + ALPHAc * x0.y;
        v[2] = a0.z * sc + ALPHAc * x0.z;
        v[3] = a0.w * sc + ALPHAc * x0.w;
        v[4] = a1.x * sc + ALPHAc * x1.x;
        v[5] = a1.y * sc + ALPHAc * x1.y;
        v[6] = a1.z * sc + ALPHAc * x1.z;
        v[7] = a1.w * sc + ALPHAc * x1.w;
        uint4 u = pack_half8s(v, 1.f);
        *(reinterpret_cast<uint4*>(g_aggh + (size_t)gw * Dd) + sub) = u;
    }
}

// copy a 64x128 fp16 tile global -> smem (stride 136), coalesced uint4
__device__ __forceinline__ void stage_tile(__half* Ah, const __half* __restrict__ Ab,
                                           int tid) {
#pragma unroll
    for (int it = 0; it < 4; ++it) {
        int idx = it * 256 + tid;            // 1024 uint4 total
        int row = idx >> 4, c8 = idx & 15;
        uint4 u = __ldg(reinterpret_cast<const uint4*>(Ab + (size_t)row * Dd) + c8);
        *reinterpret_cast<uint4*>(Ah + row * 136 + c8 * 8) = u;
    }
}

// ---------------- layer-1 GEMM + fused z-projection + x@Gx slice --------------
#define GB1_BLOCKS ((Nn + 63) / 64)                          // 782
#define XG_BLOCKS  ((Nn + 63) / 64)                          // 782
__launch_bounds__(256)
__global__ void k_gemm1(const float* __restrict__ b1, const float* __restrict__ x,
                        float* __restrict__ out) {
    __shared__ __align__(16) __half Ah[64 * 136];   // 17408 B
    __shared__ __align__(16) float  Cs[64 * 132];   // 33792 B
    int tid = threadIdx.x;
    int warp = tid >> 5;
    int ty = tid >> 4, tx = tid & 15;
    int wr = warp >> 1, wc = warp & 1;

    if (blockIdx.x >= GB1_BLOCKS) {
        // ---- light path: out = x @ Gx + c
        int n0 = (blockIdx.x - GB1_BLOCKS) << 6;
#pragma unroll
        for (int it = 0; it < 8; ++it) {
            int idx = it * 256 + tid;              // 2048
            int row = idx >> 5, c4 = idx & 31;
            int n = n0 + row;
            float4 v = (n < Nn)
                ? __ldg(reinterpret_cast<const float4*>(x + (size_t)n * Dd) + c4)
                : make_float4(0.f, 0.f, 0.f, 0.f);
            __half2 p0 = __floats2half2_rn(v.x, v.y);
            __half2 p1 = __floats2half2_rn(v.z, v.w);
            uint2 u;
            u.x = *reinterpret_cast<unsigned*>(&p0);
            u.y = *reinterpret_cast<unsigned*>(&p1);
            *reinterpret_cast<uint2*>(Ah + row * 136 + c4 * 4) = u;
        }
        __syncthreads();
        wmma::fragment<wmma::accumulator, 16, 16, 16, float> acc[2];
#pragma unroll
        for (int f = 0; f < 2; ++f) wmma::fill_fragment(acc[f], 0.f);
#pragma unroll
        for (int k = 0; k < 8; ++k) {
            wmma::fragment<wmma::matrix_a, 16, 16, 16, __half, wmma::row_major> af;
            wmma::load_matrix_sync(af, Ah + (wr * 16) * 136 + k * 16, 136);
#pragma unroll
            for (int f = 0; f < 2; ++f) {
                wmma::fragment<wmma::matrix_b, 16, 16, 16, __half, wmma::row_major> bf;
                wmma::load_matrix_sync(bf, g_Gxh + (k * 16) * OUTD + wc * 32 + f * 16, OUTD);
                wmma::mma_sync(acc[f], af, bf, acc[f]);
            }
        }
#pragma unroll
        for (int f = 0; f < 2; ++f)
            wmma::store_matrix_sync(Cs + (wr * 16) * 68 + wc * 32 + f * 16, acc[f], 68,
                                    wmma::mem_row_major);
        __syncthreads();
#pragma unroll
        for (int it = 0; it < 8; ++it) {
            int idx = it * 256 + tid;
            int row = idx >> 5, cp = idx & 31;
            int n = n0 + row;
            if (n < Nn) {
                float2 p;
                p.x = Cs[row * 68 + cp * 2]     + g_c[cp * 2];
                p.y = Cs[row * 68 + cp * 2 + 1] + g_c[cp * 2 + 1];
                *(reinterpret_cast<float2*>(out + (size_t)n * OUTD) + cp) = p;
            }
        }
        return;
    }

    // ---- heavy path: h1 tile via 3 relation GEMMs, then z_r projection
    int n0 = blockIdx.x << 6;
    float hacc[4][8];
#pragma unroll
    for (int i = 0; i < 4; ++i)
#pragma unroll
        for (int j = 0; j < 8; ++j) hacc[i][j] = 0.f;

    for (int r = 0; r < Rr; ++r) {
        if (r > 0) __syncthreads();
        stage_tile(Ah, g_aggh + ((size_t)r * Nn + n0) * Dd, tid);
        __syncthreads();

        wmma::fragment<wmma::accumulator, 16, 16, 16, float> acc[4];
#pragma unroll
        for (int f = 0; f < 4; ++f) wmma::fill_fragment(acc[f], 0.f);
        const __half* Bg = g_W1h + (size_t)r * Dd * Dd;
#pragma unroll
        for (int k = 0; k < 8; ++k) {
            wmma::fragment<wmma::matrix_a, 16, 16, 16, __half, wmma::row_major> af;
            wmma::load_matrix_sync(af, Ah + (wr * 16) * 136 + k * 16, 136);
#pragma unroll
            for (int f = 0; f < 4; ++f) {
                wmma::fragment<wmma::matrix_b, 16, 16, 16, __half, wmma::row_major> bf;
                wmma::load_matrix_sync(bf, Bg + (k * 16) * Dd + wc * 64 + f * 16, Dd);
                wmma::mma_sync(acc[f], af, bf, acc[f]);
            }
        }
#pragma unroll
        for (int f = 0; f < 4; ++f)
            wmma::store_matrix_sync(Cs + (wr * 16) * 132 + wc * 64 + f * 16, acc[f], 132,
                                    wmma::mem_row_major);
        __syncthreads();

#pragma unroll
        for (int i = 0; i < 4; ++i) {
            int row = ty * 4 + i;
#pragma unroll
            for (int j = 0; j < 8; ++j) {
                int col = tx * 8 + j;
                float v = Cs[row * 132 + col] + b1[r * Dd + col];
                v = v >= 0.f ? v : SLOPEc * v;
                hacc[i][j] += v * (1.f / 3.f);
            }
        }
    }

    // z_r = (h1 * dinv_out_r) @ G_r straight from registers
    for (int r = 0; r < Rr; ++r) {
        __syncthreads();
#pragma unroll
        for (int i = 0; i < 4; ++i) {
            int row = ty * 4 + i;
            int n = n0 + row;
            float s = (n < Nn) ? __ldg(g_dinv_out + r * Nn + n) : 0.f;
            uint4 u = pack_half8s(hacc[i], s);
            *reinterpret_cast<uint4*>(Ah + row * 136 + tx * 8) = u;
        }
        __syncthreads();

        wmma::fragment<wmma::accumulator, 16, 16, 16, float> acc2[2];
#pragma unroll
        for (int f = 0; f < 2; ++f) wmma::fill_fragment(acc2[f], 0.f);
        const __half* Bb = g_Gh + (size_t)r * Dd * OUTD;
#pragma unroll
        for (int k = 0; k < 8; ++k) {
            wmma::fragment<wmma::matrix_a, 16, 16, 16, __half, wmma::row_major> af;
            wmma::load_matrix_sync(af, Ah + (wr * 16) * 136 + k * 16, 136);
#pragma unroll
            for (int f = 0; f < 2; ++f) {
                wmma::fragment<wmma::matrix_b, 16, 16, 16, __half, wmma::row_major> bf;
                wmma::load_matrix_sync(bf, Bb + (k * 16) * OUTD + wc * 32 + f * 16, OUTD);
                wmma::mma_sync(acc2[f], af, bf, acc2[f]);
            }
        }
#pragma unroll
        for (int f = 0; f < 2; ++f)
            wmma::store_matrix_sync(Cs + (wr * 16) * 68 + wc * 32 + f * 16, acc2[f], 68,
                                    wmma::mem_row_major);
        __syncthreads();

#pragma unroll
        for (int it = 0; it < 8; ++it) {
            int idx = it * 256 + tid;        // 2048
            int row = idx >> 5, cp = idx & 31;
            int n = n0 + row;
            if (n < Nn) {
                __half2 p = __floats2half2_rn(Cs[row * 68 + cp * 2], Cs[row * 68 + cp * 2 + 1]);
                *(reinterpret_cast<unsigned*>(g_z + ((size_t)r * Nn + n) * OUTD) + cp) =
                    *reinterpret_cast<unsigned*>(&p);
            }
        }
    }
}

// ---------------- combine: half-warp-wide z rows, red.v4 into out --------------
__launch_bounds__(256)
__global__ void k_combine(float* __restrict__ out) {
    int gw = (blockIdx.x * blockDim.x + threadIdx.x) >> 5;   // (r,n)
    if (gw >= Rr * Nn) return;
    int lane = threadIdx.x & 31;
    int half = lane >> 4;          // 0: edge e, 1: edge e+1
    int sub  = lane & 15;          // cols [sub*4, sub*4+4)
    int n = gw % Nn;
    const __half* zb = g_z + (size_t)(gw / Nn) * Nn * OUTD;

    int beg = __ldg(g_rowstart + gw);
    int end = beg + __ldg(g_deg_in + gw);
    float4 acc = make_float4(0.f, 0.f, 0.f, 0.f);
    int e = beg;
#pragma unroll 1
    for (; e + 8 <= end; e += 8) {
        unsigned e0 = __ldg(g_col + e + 0 + half);
        unsigned e1 = __ldg(g_col + e + 2 + half);
        unsigned e2 = __ldg(g_col + e + 4 + half);
        unsigned e3 = __ldg(g_col + e + 6 + half);
        uint2 u0 = __ldg(reinterpret_cast<const uint2*>(zb + (size_t)(e0 & 0xffffu) * OUTD) + sub);
        uint2 u1 = __ldg(reinterpret_cast<const uint2*>(zb + (size_t)(e1 & 0xffffu) * OUTD) + sub);
        uint2 u2 = __ldg(reinterpret_cast<const uint2*>(zb + (size_t)(e2 & 0xffffu) * OUTD) + sub);
        uint2 u3 = __ldg(reinterpret_cast<const uint2*>(zb + (size_t)(e3 & 0xffffu) * OUTD) + sub);
        acc_h4(acc, u0); acc_h4(acc, u1); acc_h4(acc, u2); acc_h4(acc, u3);
    }
#pragma unroll 1
    for (; e < end; e += 2) {
        if (e + half < end) {
            unsigned e0 = __ldg(g_col + e + half);
            uint2 u0 = __ldg(reinterpret_cast<const uint2*>(zb + (size_t)(e0 & 0xffffu) * OUTD) + sub);
            acc_h4(acc, u0);
        }
    }
    // merge half-warps (full-warp shfl before divergence)
    acc.x += __shfl_xor_sync(0xffffffffu, acc.x, 16);
    acc.y += __shfl_xor_sync(0xffffffffu, acc.y, 16);
    acc.z += __shfl_xor_sync(0xffffffffu, acc.z, 16);
    acc.w += __shfl_xor_sync(0xffffffffu, acc.w, 16);

    if (half == 0) {
        float di = __ldg(g_dinv_in + gw);
        float v0 = acc.x * di, v1 = acc.y * di, v2 = acc.z * di, v3 = acc.w * di;
        float* p = out + (size_t)n * OUTD + sub * 4;
        asm volatile("red.global.add.v4.f32 [%0], {%1,%2,%3,%4};"
                     :: "l"(p), "f"(v0), "f"(v1), "f"(v2), "f"(v3) : "memory");
    }
}

// ---------------- launch ------------------------------------------------------
extern "C" void kernel_launch(void* const* d_in, const int* in_sizes, int n_in,
                              void* d_out, int out_size) {
    const float* x    = (const float*)d_in[0];
    const int*   src  = (const int*)  d_in[1];
    const int*   dst  = (const int*)  d_in[2];
    const float* W1   = (const float*)d_in[3];
    const float* b1   = (const float*)d_in[4];
    const float* W2   = (const float*)d_in[5];
    const float* b2   = (const float*)d_in[6];
    const float* Wlin = (const float*)d_in[7];
    const float* blin = (const float*)d_in[8];
    float* out = (float*)d_out;

    k_init<<<(Rr * Nn + 255) / 256, 256>>>();
    k_degree_prep<<<DEG_BLOCKS + P1_BLOCKS + PW1_BLOCKS, 256>>>(src, dst, W2, Wlin, W1);
    k_rowstart_prep<<<RS_BLOCKS + P2_BLOCKS, 256>>>(b2, Wlin, blin);
    k_csrfill_prescale<<<CF_BLOCKS + PS_BLOCKS, 256>>>(src, dst, x);

    const int gather_blocks = (Rr * Nn * 32 + 255) / 256;   // one warp per (r,n)
    k_gather1<<<gather_blocks, 256>>>();
    k_gemm1<<<GB1_BLOCKS + XG_BLOCKS, 256>>>(b1, x, out);
    k_combine<<<gather_blocks, 256>>>(out);
}

// round 16
// speedup vs baseline: 1.1201x; 1.0146x over previous
#include <cuda_runtime.h>
#include <cuda_fp16.h>
#include <mma.h>
#include <cstdint>

using namespace nvcuda;

// Problem constants (fixed by dataset)
#define Nn 50000
#define Dd 128
#define Rr 3
#define Ee 800000
#define OUTD 64
#define ALPHAc 0.5f
#define BETA1c 0.6931471805599453f   // ln 2
#define BETA2c 0.4054651081081644f   // ln 1.5
#define SLOPEc 0.01f

// ---------------- scratch (device globals; no allocations allowed) ----------
__device__ __align__(256) __half g_aggh[((size_t)Rr * Nn + 64) * Dd]; // layer-1 operand, padded
__device__ __align__(256) __half g_xh  [((size_t)Nn + 64) * Dd];      // plain fp16 x (L2-resident)
__device__ __align__(256) __half g_z   [(size_t)Rr * Nn * OUTD];      // z_r = (h1*d_out_r) @ G_r
__device__ __align__(256) __half g_W1h [Rr * Dd * Dd];                // b1*W1 + (1-b1)*I
__device__ __align__(256) __half g_Gh  [Rr * Dd * OUTD];
__device__ __align__(256) __half g_Gxh [Dd * OUTD];
__device__ int      g_deg_out[Rr * Nn];
__device__ int      g_deg_in[Rr * Nn];
__device__ float    g_dinv_out[Rr * Nn];
__device__ float    g_dinv_in[Rr * Nn];
__device__ int2     g_rowdeg[Rr * Nn];        // {rowstart, deg_in} packed
__device__ int      g_fillcur[Rr * Nn];
__device__ unsigned g_col[(size_t)Rr * Ee];   // packed: src(16) | fp16 dinv_out(16)
__device__ int      g_cursor[Rr];
__device__ float    g_G[Rr * Dd * OUTD];
__device__ float    g_c[OUTD];

// ---------------- init small state -------------------------------------------
__global__ void k_init() {
    int i = blockIdx.x * blockDim.x + threadIdx.x;
    if (i < Rr * Nn) { g_deg_out[i] = 0; g_deg_in[i] = 0; }
    if (i < Rr) g_cursor[i] = 0;
}

// ---------------- launch A: degree histogram + prep1 + prepw1 -----------------
#define DEG_BLOCKS  ((Rr * Ee + 255) / 256)                  // 9375
#define P1_BLOCKS   ((Rr * Dd * OUTD + 255) / 256)           // 96
#define PW1_BLOCKS  ((Rr * Dd * Dd + 255) / 256)             // 192
__global__ void k_degree_prep(const int* __restrict__ src, const int* __restrict__ dst,
                              const float* __restrict__ W2, const float* __restrict__ Wlin,
                              const float* __restrict__ W1) {
    int b = blockIdx.x;
    int t = threadIdx.x;
    if (b < DEG_BLOCKS) {
        int i = b * 256 + t;
        if (i >= Rr * Ee) return;
        int r = i / Ee;
        atomicAdd(&g_deg_out[r * Nn + src[i]], 1);
        atomicAdd(&g_deg_in [r * Nn + dst[i]], 1);
    } else if (b < DEG_BLOCKS + P1_BLOCKS) {
        int idx = (b - DEG_BLOCKS) * 256 + t;
        if (idx >= Rr * Dd * OUTD) return;
        int r = idx / (Dd * OUTD);
        int rem = idx % (Dd * OUTD);
        int i = rem / OUTD, j = rem % OUTD;
        const float* wrow = W2 + ((size_t)r * Dd + i) * Dd;
        float s = 0.f;
#pragma unroll 8
        for (int k = 0; k < Dd; ++k) s += wrow[k] * Wlin[k * OUTD + j];
        g_G[idx] = BETA2c * s + (1.f - BETA2c) * Wlin[rem];
    } else {
        int idx = (b - DEG_BLOCKS - P1_BLOCKS) * 256 + t;
        if (idx >= Rr * Dd * Dd) return;
        int ij = idx % (Dd * Dd);
        int i = ij >> 7, j = ij & 127;
        float v = BETA1c * W1[idx] + ((i == j) ? (1.f - BETA1c) : 0.f);
        g_W1h[idx] = __float2half(v);
    }
}

// ---------------- launch B: row starts + dinv + prep2 --------------------------
#define RS_XBLOCKS ((Nn + 255) / 256)                        // 196
#define RS_BLOCKS  (RS_XBLOCKS * Rr)                         // 588
#define P2_BLOCKS  ((Dd * OUTD + 255) / 256)                 // 32
__global__ void k_rowstart_prep(const float* __restrict__ b2, const float* __restrict__ Wlin,
                                const float* __restrict__ blin) {
    int b = blockIdx.x;
    int t = threadIdx.x;
    if (b < RS_BLOCKS) {
        int r = b / RS_XBLOCKS;
        int n = (b % RS_XBLOCKS) * 256 + t;
        int lane = t & 31;
        int d = (n < Nn) ? g_deg_in[r * Nn + n] : 0;
        int incl = d;
#pragma unroll
        for (int o = 1; o < 32; o <<= 1) {
            int v = __shfl_up_sync(0xffffffffu, incl, o);
            if (lane >= o) incl += v;
        }
        int total = __shfl_sync(0xffffffffu, incl, 31);
        int base = 0;
        if (lane == 31) base = atomicAdd(&g_cursor[r], total);
        base = __shfl_sync(0xffffffffu, base, 31);
        if (n < Nn) {
            int start = r * Ee + base + incl - d;
            g_rowdeg [r * Nn + n] = make_int2(start, d);
            g_fillcur[r * Nn + n] = start;
            int di = d < 1 ? 1 : d;
            g_dinv_in[r * Nn + n] = rsqrtf((float)di);
            int doo = g_deg_out[r * Nn + n]; if (doo < 1) doo = 1;
            g_dinv_out[r * Nn + n] = rsqrtf((float)doo);
        }
    } else {
        int idx = (b - RS_BLOCKS) * 256 + t;
        if (idx < Dd * OUTD) {
            float v0 = g_G[idx], v1 = g_G[Dd * OUTD + idx], v2 = g_G[2 * Dd * OUTD + idx];
            g_Gxh[idx] = __float2half((ALPHAc / 3.f) * (v0 + v1 + v2));
            const float sc = (1.f - ALPHAc) / 3.f;
            g_Gh[idx]                 = __float2half(v0 * sc);
            g_Gh[Dd * OUTD + idx]     = __float2half(v1 * sc);
            g_Gh[2 * Dd * OUTD + idx] = __float2half(v2 * sc);
        }
        if (idx < OUTD) {
            float cc = blin[idx];
            for (int k = 0; k < Dd; ++k)
                cc += (b2[k] + b2[Dd + k] + b2[2 * Dd + k]) * (1.f / 3.f) * Wlin[k * OUTD + idx];
            g_c[idx] = cc;
        }
    }
}

// ---------------- launch C: CSR fill (packed scale) + fp16 x -------------------
#define CF_BLOCKS  ((Rr * Ee + 255) / 256)                   // 9375
#define PS_BLOCKS  ((Nn * (Dd / 4) + 255) / 256)             // 6250
__global__ void k_csrfill_prescale(const int* __restrict__ src, const int* __restrict__ dst,
                                   const float* __restrict__ x) {
    int b = blockIdx.x;
    int t = threadIdx.x;
    if (b < CF_BLOCKS) {
        int i = b * 256 + t;
        if (i >= Rr * Ee) return;
        int r = i / Ee;
        int s = src[i];
        __half sh = __float2half(__ldg(g_dinv_out + r * Nn + s));
        unsigned entry = (unsigned)s |
                         ((unsigned)__half_as_ushort(sh) << 16);
        int pos = atomicAdd(&g_fillcur[r * Nn + dst[i]], 1);
        g_col[pos] = entry;
    } else {
        int i = (b - CF_BLOCKS) * 256 + t;
        if (i >= Nn * (Dd / 4)) return;
        int c4 = i & 31;
        int n = i >> 5;
        float4 v = __ldg(reinterpret_cast<const float4*>(x + (size_t)n * Dd) + c4);
        __half2 q0 = __floats2half2_rn(v.x, v.y);
        __half2 q1 = __floats2half2_rn(v.z, v.w);
        uint2 w;
        w.x = *reinterpret_cast<unsigned*>(&q0);
        w.y = *reinterpret_cast<unsigned*>(&q1);
        *reinterpret_cast<uint2*>(g_xh + (size_t)n * Dd + c4 * 4) = w;
    }
}

// ---------------- fp16 helpers --------------------------------------------------
__device__ __forceinline__ void acc_h4(float4& acc, uint2 u) {
    __half2 a = *reinterpret_cast<__half2*>(&u.x);
    __half2 b = *reinterpret_cast<__half2*>(&u.y);
    float2 fa = __half22float2(a), fb = __half22float2(b);
    acc.x += fa.x; acc.y += fa.y; acc.z += fb.x; acc.w += fb.y;
}

// accumulate 8 halfs (uint4), scaled by s, into two float4
__device__ __forceinline__ void acc_h8s(float4& a0, float4& a1, uint4 u, float s) {
    __half2 h0 = *reinterpret_cast<__half2*>(&u.x);
    __half2 h1 = *reinterpret_cast<__half2*>(&u.y);
    __half2 h2 = *reinterpret_cast<__half2*>(&u.z);
    __half2 h3 = *reinterpret_cast<__half2*>(&u.w);
    float2 f0 = __half22float2(h0), f1 = __half22float2(h1);
    float2 f2 = __half22float2(h2), f3 = __half22float2(h3);
    a0.x += s * f0.x; a0.y += s * f0.y; a0.z += s * f1.x; a0.w += s * f1.y;
    a1.x += s * f2.x; a1.y += s * f2.y; a1.z += s * f3.x; a1.w += s * f3.y;
}

// accumulate 8 halfs (uint4, unscaled) into two float4
__device__ __forceinline__ void acc_h8(float4& a0, float4& a1, uint4 u) {
    acc_h4(a0, make_uint2(u.x, u.y));
    acc_h4(a1, make_uint2(u.z, u.w));
}

// pack 8 floats (scaled) -> 8 halfs (16B)
__device__ __forceinline__ uint4 pack_half8s(const float* v, float s) {
    __half2 p0 = __floats2half2_rn(v[0] * s, v[1] * s);
    __half2 p1 = __floats2half2_rn(v[2] * s, v[3] * s);
    __half2 p2 = __floats2half2_rn(v[4] * s, v[5] * s);
    __half2 p3 = __floats2half2_rn(v[6] * s, v[7] * s);
    uint4 u;
    u.x = *reinterpret_cast<unsigned*>(&p0);
    u.y = *reinterpret_cast<unsigned*>(&p1);
    u.z = *reinterpret_cast<unsigned*>(&p2);
    u.w = *reinterpret_cast<unsigned*>(&p3);
    return u;
}

// ---------------- gather (layer 1): 16-edge pipeline, MLP=8 -------------------
// aggh = (1-a)*dinv_in * sum_e(x[src]*dout[src]) + a*x[n]
__launch_bounds__(256)
__global__ void k_gather1() {
    int gw = (blockIdx.x * blockDim.x + threadIdx.x) >> 5;   // (r,n) index
    if (gw >= Rr * Nn) return;
    int lane = threadIdx.x & 31;
    int half = lane >> 4;          // 0: edge e, 1: edge e+1
    int sub  = lane & 15;          // halfs [sub*8, sub*8+8)
    int n = gw % Nn;

    int2 rd = __ldg(g_rowdeg + gw);
    int beg = rd.x, end = rd.x + rd.y;
    float4 a0 = make_float4(0.f, 0.f, 0.f, 0.f);
    float4 a1 = make_float4(0.f, 0.f, 0.f, 0.f);
    int e = beg;
#pragma unroll 1
    for (; e + 16 <= end; e += 16) {
        unsigned e0 = __ldg(g_col + e + 0  + half);
        unsigned e1 = __ldg(g_col + e + 2  + half);
        unsigned e2 = __ldg(g_col + e + 4  + half);
        unsigned e3 = __ldg(g_col + e + 6  + half);
        unsigned e4 = __ldg(g_col + e + 8  + half);
        unsigned e5 = __ldg(g_col + e + 10 + half);
        unsigned e6 = __ldg(g_col + e + 12 + half);
        unsigned e7 = __ldg(g_col + e + 14 + half);
        uint4 u0 = __ldg(reinterpret_cast<const uint4*>(g_xh + (size_t)(e0 & 0xffffu) * Dd) + sub);
        uint4 u1 = __ldg(reinterpret_cast<const uint4*>(g_xh + (size_t)(e1 & 0xffffu) * Dd) + sub);
        uint4 u2 = __ldg(reinterpret_cast<const uint4*>(g_xh + (size_t)(e2 & 0xffffu) * Dd) + sub);
        uint4 u3 = __ldg(reinterpret_cast<const uint4*>(g_xh + (size_t)(e3 & 0xffffu) * Dd) + sub);
        uint4 u4 = __ldg(reinterpret_cast<const uint4*>(g_xh + (size_t)(e4 & 0xffffu) * Dd) + sub);
        uint4 u5 = __ldg(reinterpret_cast<const uint4*>(g_xh + (size_t)(e5 & 0xffffu) * Dd) + sub);
        uint4 u6 = __ldg(reinterpret_cast<const uint4*>(g_xh + (size_t)(e6 & 0xffffu) * Dd) + sub);
        uint4 u7 = __ldg(reinterpret_cast<const uint4*>(g_xh + (size_t)(e7 & 0xffffu) * Dd) + sub);
        acc_h8s(a0, a1, u0, __half2float(__ushort_as_half((unsigned short)(e0 >> 16))));
        acc_h8s(a0, a1, u1, __half2float(__ushort_as_half((unsigned short)(e1 >> 16))));
        acc_h8s(a0, a1, u2, __half2float(__ushort_as_half((unsigned short)(e2 >> 16))));
        acc_h8s(a0, a1, u3, __half2float(__ushort_as_half((unsigned short)(e3 >> 16))));
        acc_h8s(a0, a1, u4, __half2float(__ushort_as_half((unsigned short)(e4 >> 16))));
        acc_h8s(a0, a1, u5, __half2float(__ushort_as_half((unsigned short)(e5 >> 16))));
        acc_h8s(a0, a1, u6, __half2float(__ushort_as_half((unsigned short)(e6 >> 16))));
        acc_h8s(a0, a1, u7, __half2float(__ushort_as_half((unsigned short)(e7 >> 16))));
    }
#pragma unroll 1
    for (; e + 8 <= end; e += 8) {
        unsigned e0 = __ldg(g_col + e + 0 + half);
        unsigned e1 = __ldg(g_col + e + 2 + half);
        unsigned e2 = __ldg(g_col + e + 4 + half);
        unsigned e3 = __ldg(g_col + e + 6 + half);
        uint4 u0 = __ldg(reinterpret_cast<const uint4*>(g_xh + (size_t)(e0 & 0xffffu) * Dd) + sub);
        uint4 u1 = __ldg(reinterpret_cast<const uint4*>(g_xh + (size_t)(e1 & 0xffffu) * Dd) + sub);
        uint4 u2 = __ldg(reinterpret_cast<const uint4*>(g_xh + (size_t)(e2 & 0xffffu) * Dd) + sub);
        uint4 u3 = __ldg(reinterpret_cast<const uint4*>(g_xh + (size_t)(e3 & 0xffffu) * Dd) + sub);
        acc_h8s(a0, a1, u0, __half2float(__ushort_as_half((unsigned short)(e0 >> 16))));
        acc_h8s(a0, a1, u1, __half2float(__ushort_as_half((unsigned short)(e1 >> 16))));
        acc_h8s(a0, a1, u2, __half2float(__ushort_as_half((unsigned short)(e2 >> 16))));
        acc_h8s(a0, a1, u3, __half2float(__ushort_as_half((unsigned short)(e3 >> 16))));
    }
#pragma unroll 1
    for (; e < end; e += 2) {
        if (e + half < end) {
            unsigned e0 = __ldg(g_col + e + half);
            uint4 u0 = __ldg(reinterpret_cast<const uint4*>(g_xh + (size_t)(e0 & 0xffffu) * Dd) + sub);
            acc_h8s(a0, a1, u0, __half2float(__ushort_as_half((unsigned short)(e0 >> 16))));
        }
    }
    // merge the two half-warps (full-warp shfl before any divergence)
    a0.x += __shfl_xor_sync(0xffffffffu, a0.x, 16);
    a0.y += __shfl_xor_sync(0xffffffffu, a0.y, 16);
    a0.z += __shfl_xor_sync(0xffffffffu, a0.z, 16);
    a0.w += __shfl_xor_sync(0xffffffffu, a0.w, 16);
    a1.x += __shfl_xor_sync(0xffffffffu, a1.x, 16);
    a1.y += __shfl_xor_sync(0xffffffffu, a1.y, 16);
    a1.z += __shfl_xor_sync(0xffffffffu, a1.z, 16);
    a1.w += __shfl_xor_sync(0xffffffffu, a1.w, 16);

    if (half == 0) {
        float sc = __ldg(g_dinv_in + gw) * (1.f - ALPHAc);
        uint4 xv = __ldg(reinterpret_cast<const uint4*>(g_xh + (size_t)n * Dd) + sub);
        float4 x0 = make_float4(0.f, 0.f, 0.f, 0.f);
        float4 x1 = make_float4(0.f, 0.f, 0.f, 0.f);
        acc_h8(x0, x1, xv);
        float v[8];
        v[0] = a0.x * sc + ALPHAc * x0.x;
        v[1] = a0.y * sc + ALPHAc * x0.y;
        v[2] = a0.z * sc + ALPHAc * x0.z;
        v[3] = a0.w * sc + ALPHAc * x0.w;
        v[4] = a1.x * sc + ALPHAc * x1.x;
        v[5] = a1.y * sc + ALPHAc * x1.y;
        v[6] = a1.z * sc + ALPHAc * x1.z;
        v[7] = a1.w * sc + ALPHAc * x1.w;
        uint4 u = pack_half8s(v, 1.f);
        *(reinterpret_cast<uint4*>(g_aggh + (size_t)gw * Dd) + sub) = u;
    }
}

// copy a 64x128 fp16 tile global -> smem (stride 136), coalesced uint4
__device__ __forceinline__ void stage_tile(__half* Ah, const __half* __restrict__ Ab,
                                           int tid) {
#pragma unroll
    for (int it = 0; it < 4; ++it) {
        int idx = it * 256 + tid;            // 1024 uint4 total
        int row = idx >> 4, c8 = idx & 15;
        uint4 u = __ldg(reinterpret_cast<const uint4*>(Ab + (size_t)row * Dd) + c8);
        *reinterpret_cast<uint4*>(Ah + row * 136 + c8 * 8) = u;
    }
}

// ---------------- layer-1 GEMM + fused z-projection + x@Gx slice --------------
#define GB1_BLOCKS ((Nn + 63) / 64)                          // 782
#define XG_BLOCKS  ((Nn + 63) / 64)                          // 782
__launch_bounds__(256)
__global__ void k_gemm1(const float* __restrict__ b1, const float* __restrict__ x,
                        float* __restrict__ out) {
    __shared__ __align__(16) __half Ah[64 * 136];   // 17408 B
    __shared__ __align__(16) float  Cs[64 * 132];   // 33792 B
    int tid = threadIdx.x;
    int warp = tid >> 5;
    int ty = tid >> 4, tx = tid & 15;
    int wr = warp >> 1, wc = warp & 1;

    if (blockIdx.x >= GB1_BLOCKS) {
        // ---- light path: out = x @ Gx + c
        int n0 = (blockIdx.x - GB1_BLOCKS) << 6;
#pragma unroll
        for (int it = 0; it < 8; ++it) {
            int idx = it * 256 + tid;              // 2048
            int row = idx >> 5, c4 = idx & 31;
            int n = n0 + row;
            float4 v = (n < Nn)
                ? __ldg(reinterpret_cast<const float4*>(x + (size_t)n * Dd) + c4)
                : make_float4(0.f, 0.f, 0.f, 0.f);
            __half2 p0 = __floats2half2_rn(v.x, v.y);
            __half2 p1 = __floats2half2_rn(v.z, v.w);
            uint2 u;
            u.x = *reinterpret_cast<unsigned*>(&p0);
            u.y = *reinterpret_cast<unsigned*>(&p1);
            *reinterpret_cast<uint2*>(Ah + row * 136 + c4 * 4) = u;
        }
        __syncthreads();
        wmma::fragment<wmma::accumulator, 16, 16, 16, float> acc[2];
#pragma unroll
        for (int f = 0; f < 2; ++f) wmma::fill_fragment(acc[f], 0.f);
#pragma unroll
        for (int k = 0; k < 8; ++k) {
            wmma::fragment<wmma::matrix_a, 16, 16, 16, __half, wmma::row_major> af;
            wmma::load_matrix_sync(af, Ah + (wr * 16) * 136 + k * 16, 136);
#pragma unroll
            for (int f = 0; f < 2; ++f) {
                wmma::fragment<wmma::matrix_b, 16, 16, 16, __half, wmma::row_major> bf;
                wmma::load_matrix_sync(bf, g_Gxh + (k * 16) * OUTD + wc * 32 + f * 16, OUTD);
                wmma::mma_sync(acc[f], af, bf, acc[f]);
            }
        }
#pragma unroll
        for (int f = 0; f < 2; ++f)
            wmma::store_matrix_sync(Cs + (wr * 16) * 68 + wc * 32 + f * 16, acc[f], 68,
                                    wmma::mem_row_major);
        __syncthreads();
#pragma unroll
        for (int it = 0; it < 8; ++it) {
            int idx = it * 256 + tid;
            int row = idx >> 5, cp = idx & 31;
            int n = n0 + row;
            if (n < Nn) {
                float2 p;
                p.x = Cs[row * 68 + cp * 2]     + g_c[cp * 2];
                p.y = Cs[row * 68 + cp * 2 + 1] + g_c[cp * 2 + 1];
                *(reinterpret_cast<float2*>(out + (size_t)n * OUTD) + cp) = p;
            }
        }
        return;
    }

    // ---- heavy path: h1 tile via 3 relation GEMMs, then z_r projection
    int n0 = blockIdx.x << 6;
    float hacc[4][8];
#pragma unroll
    for (int i = 0; i < 4; ++i)
#pragma unroll
        for (int j = 0; j < 8; ++j) hacc[i][j] = 0.f;

    for (int r = 0; r < Rr; ++r) {
        if (r > 0) __syncthreads();
        stage_tile(Ah, g_aggh + ((size_t)r * Nn + n0) * Dd, tid);
        __syncthreads();

        wmma::fragment<wmma::accumulator, 16, 16, 16, float> acc[4];
#pragma unroll
        for (int f = 0; f < 4; ++f) wmma::fill_fragment(acc[f], 0.f);
        const __half* Bg = g_W1h + (size_t)r * Dd * Dd;
#pragma unroll
        for (int k = 0; k < 8; ++k) {
            wmma::fragment<wmma::matrix_a, 16, 16, 16, __half, wmma::row_major> af;
            wmma::load_matrix_sync(af, Ah + (wr * 16) * 136 + k * 16, 136);
#pragma unroll
            for (int f = 0; f < 4; ++f) {
                wmma::fragment<wmma::matrix_b, 16, 16, 16, __half, wmma::row_major> bf;
                wmma::load_matrix_sync(bf, Bg + (k * 16) * Dd + wc * 64 + f * 16, Dd);
                wmma::mma_sync(acc[f], af, bf, acc[f]);
            }
        }
#pragma unroll
        for (int f = 0; f < 4; ++f)
            wmma::store_matrix_sync(Cs + (wr * 16) * 132 + wc * 64 + f * 16, acc[f], 132,
                                    wmma::mem_row_major);
        __syncthreads();

#pragma unroll
        for (int i = 0; i < 4; ++i) {
            int row = ty * 4 + i;
#pragma unroll
            for (int j = 0; j < 8; ++j) {
                int col = tx * 8 + j;
                float v = Cs[row * 132 + col] + b1[r * Dd + col];
                v = v >= 0.f ? v : SLOPEc * v;
                hacc[i][j] += v * (1.f / 3.f);
            }
        }
    }

    // z_r = (h1 * dinv_out_r) @ G_r straight from registers
    for (int r = 0; r < Rr; ++r) {
        __syncthreads();
#pragma unroll
        for (int i = 0; i < 4; ++i) {
            int row = ty * 4 + i;
            int n = n0 + row;
            float s = (n < Nn) ? __ldg(g_dinv_out + r * Nn + n) : 0.f;
            uint4 u = pack_half8s(hacc[i], s);
            *reinterpret_cast<uint4*>(Ah + row * 136 + tx * 8) = u;
        }
        __syncthreads();

        wmma::fragment<wmma::accumulator, 16, 16, 16, float> acc2[2];
#pragma unroll
        for (int f = 0; f < 2; ++f) wmma::fill_fragment(acc2[f], 0.f);
        const __half* Bb = g_Gh + (size_t)r * Dd * OUTD;
#pragma unroll
        for (int k = 0; k < 8; ++k) {
            wmma::fragment<wmma::matrix_a, 16, 16, 16, __half, wmma::row_major> af;
            wmma::load_matrix_sync(af, Ah + (wr * 16) * 136 + k * 16, 136);
#pragma unroll
            for (int f = 0; f < 2; ++f) {
                wmma::fragment<wmma::matrix_b, 16, 16, 16, __half, wmma::row_major> bf;
                wmma::load_matrix_sync(bf, Bb + (k * 16) * OUTD + wc * 32 + f * 16, OUTD);
                wmma::mma_sync(acc2[f], af, bf, acc2[f]);
            }
        }
#pragma unroll
        for (int f = 0; f < 2; ++f)
            wmma::store_matrix_sync(Cs + (wr * 16) * 68 + wc * 32 + f * 16, acc2[f], 68,
                                    wmma::mem_row_major);
        __syncthreads();

#pragma unroll
        for (int it = 0; it < 8; ++it) {
            int idx = it * 256 + tid;        // 2048
            int row = idx >> 5, cp = idx & 31;
            int n = n0 + row;
            if (n < Nn) {
                __half2 p = __floats2half2_rn(Cs[row * 68 + cp * 2], Cs[row * 68 + cp * 2 + 1]);
                *(reinterpret_cast<unsigned*>(g_z + ((size_t)r * Nn + n) * OUTD) + cp) =
                    *reinterpret_cast<unsigned*>(&p);
            }
        }
    }
}

// ---------------- combine: 16-edge pipeline, red.v4 into out -------------------
__launch_bounds__(256)
__global__ void k_combine(float* __restrict__ out) {
    int gw = (blockIdx.x * blockDim.x + threadIdx.x) >> 5;   // (r,n)
    if (gw >= Rr * Nn) return;
    int lane = threadIdx.x & 31;
    int half = lane >> 4;          // 0: edge e, 1: edge e+1
    int sub  = lane & 15;          // cols [sub*4, sub*4+4)
    int n = gw % Nn;
    const __half* zb = g_z + (size_t)(gw / Nn) * Nn * OUTD;

    int2 rd = __ldg(g_rowdeg + gw);
    int beg = rd.x, end = rd.x + rd.y;
    float4 acc = make_float4(0.f, 0.f, 0.f, 0.f);
    int e = beg;
#pragma unroll 1
    for (; e + 16 <= end; e += 16) {
        unsigned e0 = __ldg(g_col + e + 0  + half);
        unsigned e1 = __ldg(g_col + e + 2  + half);
        unsigned e2 = __ldg(g_col + e + 4  + half);
        unsigned e3 = __ldg(g_col + e + 6  + half);
        unsigned e4 = __ldg(g_col + e + 8  + half);
        unsigned e5 = __ldg(g_col + e + 10 + half);
        unsigned e6 = __ldg(g_col + e + 12 + half);
        unsigned e7 = __ldg(g_col + e + 14 + half);
        uint2 u0 = __ldg(reinterpret_cast<const uint2*>(zb + (size_t)(e0 & 0xffffu) * OUTD) + sub);
        uint2 u1 = __ldg(reinterpret_cast<const uint2*>(zb + (size_t)(e1 & 0xffffu) * OUTD) + sub);
        uint2 u2 = __ldg(reinterpret_cast<const uint2*>(zb + (size_t)(e2 & 0xffffu) * OUTD) + sub);
        uint2 u3 = __ldg(reinterpret_cast<const uint2*>(zb + (size_t)(e3 & 0xffffu) * OUTD) + sub);
        uint2 u4 = __ldg(reinterpret_cast<const uint2*>(zb + (size_t)(e4 & 0xffffu) * OUTD) + sub);
        uint2 u5 = __ldg(reinterpret_cast<const uint2*>(zb + (size_t)(e5 & 0xffffu) * OUTD) + sub);
        uint2 u6 = __ldg(reinterpret_cast<const uint2*>(zb + (size_t)(e6 & 0xffffu) * OUTD) + sub);
        uint2 u7 = __ldg(reinterpret_cast<const uint2*>(zb + (size_t)(e7 & 0xffffu) * OUTD) + sub);
        acc_h4(acc, u0); acc_h4(acc, u1); acc_h4(acc, u2); acc_h4(acc, u3);
        acc_h4(acc, u4); acc_h4(acc, u5); acc_h4(acc, u6); acc_h4(acc, u7);
    }
#pragma unroll 1
    for (; e + 8 <= end; e += 8) {
        unsigned e0 = __ldg(g_col + e + 0 + half);
        unsigned e1 = __ldg(g_col + e + 2 + half);
        unsigned e2 = __ldg(g_col + e + 4 + half);
        unsigned e3 = __ldg(g_col + e + 6 + half);
        uint2 u0 = __ldg(reinterpret_cast<const uint2*>(zb + (size_t)(e0 & 0xffffu) * OUTD) + sub);
        uint2 u1 = __ldg(reinterpret_cast<const uint2*>(zb + (size_t)(e1 & 0xffffu) * OUTD) + sub);
        uint2 u2 = __ldg(reinterpret_cast<const uint2*>(zb + (size_t)(e2 & 0xffffu) * OUTD) + sub);
        uint2 u3 = __ldg(reinterpret_cast<const uint2*>(zb + (size_t)(e3 & 0xffffu) * OUTD) + sub);
        acc_h4(acc, u0); acc_h4(acc, u1); acc_h4(acc, u2); acc_h4(acc, u3);
    }
#pragma unroll 1
    for (; e < end; e += 2) {
        if (e + half < end) {
            unsigned e0 = __ldg(g_col + e + half);
            uint2 u0 = __ldg(reinterpret_cast<const uint2*>(zb + (size_t)(e0 & 0xffffu) * OUTD) + sub);
            acc_h4(acc, u0);
        }
    }
    // merge half-warps (full-warp shfl before divergence)
    acc.x += __shfl_xor_sync(0xffffffffu, acc.x, 16);
    acc.y += __shfl_xor_sync(0xffffffffu, acc.y, 16);
    acc.z += __shfl_xor_sync(0xffffffffu, acc.z, 16);
    acc.w += __shfl_xor_sync(0xffffffffu, acc.w, 16);

    if (half == 0) {
        float di = __ldg(g_dinv_in + gw);
        float v0 = acc.x * di, v1 = acc.y * di, v2 = acc.z * di, v3 = acc.w * di;
        float* p = out + (size_t)n * OUTD + sub * 4;
        asm volatile("red.global.add.v4.f32 [%0], {%1,%2,%3,%4};"
                     :: "l"(p), "f"(v0), "f"(v1), "f"(v2), "f"(v3) : "memory");
    }
}

// ---------------- launch ------------------------------------------------------
extern "C" void kernel_launch(void* const* d_in, const int* in_sizes, int n_in,
                              void* d_out, int out_size) {
    const float* x    = (const float*)d_in[0];
    const int*   src  = (const int*)  d_in[1];
    const int*   dst  = (const int*)  d_in[2];
    const float* W1   = (const float*)d_in[3];
    const float* b1   = (const float*)d_in[4];
    const float* W2   = (const float*)d_in[5];
    const float* b2   = (const float*)d_in[6];
    const float* Wlin = (const float*)d_in[7];
    const float* blin = (const float*)d_in[8];
    float* out = (float*)d_out;

    k_init<<<(Rr * Nn + 255) / 256, 256>>>();
    k_degree_prep<<<DEG_BLOCKS + P1_BLOCKS + PW1_BLOCKS, 256>>>(src, dst, W2, Wlin, W1);
    k_rowstart_prep<<<RS_BLOCKS + P2_BLOCKS, 256>>>(b2, Wlin, blin);
    k_csrfill_prescale<<<CF_BLOCKS + PS_BLOCKS, 256>>>(src, dst, x);

    const int gather_blocks = (Rr * Nn * 32 + 255) / 256;   // one warp per (r,n)
    k_gather1<<<gather_blocks, 256>>>();
    k_gemm1<<<GB1_BLOCKS + XG_BLOCKS, 256>>>(b1, x, out);
    k_combine<<<gather_blocks, 256>>>(out);
}

// round 17
// speedup vs baseline: 1.1247x; 1.0041x over previous
#include <cuda_runtime.h>
#include <cuda_fp16.h>
#include <mma.h>
#include <cstdint>

using namespace nvcuda;

// Problem constants (fixed by dataset)
#define Nn 50000
#define Dd 128
#define Rr 3
#define Ee 800000
#define OUTD 64
#define ALPHAc 0.5f
#define BETA1c 0.6931471805599453f   // ln 2
#define BETA2c 0.4054651081081644f   // ln 1.5
#define SLOPEc 0.01f

// ---------------- scratch (device globals; no allocations allowed) ----------
// NOTE: zero-init invariant — g_deg_out/g_deg_in/g_cursor are zero at module
// load and are re-zeroed at the END of each call (launch C), so no init launch.
__device__ __align__(256) __half g_aggh[((size_t)Rr * Nn + 64) * Dd]; // layer-1 operand, padded
__device__ __align__(256) __half g_xh  [((size_t)Nn + 64) * Dd];      // plain fp16 x (L2-resident)
__device__ __align__(256) __half g_z   [(size_t)Rr * Nn * OUTD];      // z_r = (h1*d_out_r) @ G_r
__device__ __align__(256) __half g_W1h [Rr * Dd * Dd];                // b1*W1 + (1-b1)*I
__device__ __align__(256) __half g_Gh  [Rr * Dd * OUTD];
__device__ __align__(256) __half g_Gxh [Dd * OUTD];
__device__ int      g_deg_out[Rr * Nn];
__device__ int      g_deg_in[Rr * Nn];
__device__ float    g_dinv_out[Rr * Nn];
__device__ float    g_dinv_in[Rr * Nn];
__device__ int2     g_rowdeg[Rr * Nn];        // {rowstart, deg_in} packed
__device__ int      g_fillcur[Rr * Nn];
__device__ unsigned g_col[(size_t)Rr * Ee];   // packed: src(16) | fp16 dinv_out(16)
__device__ int      g_cursor[Rr];
__device__ float    g_G[Rr * Dd * OUTD];
__device__ float    g_c[OUTD];

// ---------------- launch A: degree histogram + fp16 prescale + prep1 + prepw1 --
#define DEG_BLOCKS  ((Rr * Ee + 255) / 256)                  // 9375
#define PS_BLOCKS   ((Nn * (Dd / 4) + 255) / 256)            // 6250
#define P1_BLOCKS   ((Rr * Dd * OUTD + 255) / 256)           // 96
#define PW1_BLOCKS  ((Rr * Dd * Dd + 255) / 256)             // 192
__global__ void k_degree_prep(const int* __restrict__ src, const int* __restrict__ dst,
                              const float* __restrict__ W2, const float* __restrict__ Wlin,
                              const float* __restrict__ W1, const float* __restrict__ x) {
    int b = blockIdx.x;
    int t = threadIdx.x;
    if (b < DEG_BLOCKS) {
        int i = b * 256 + t;
        if (i >= Rr * Ee) return;
        int r = i / Ee;
        atomicAdd(&g_deg_out[r * Nn + src[i]], 1);
        atomicAdd(&g_deg_in [r * Nn + dst[i]], 1);
    } else if (b < DEG_BLOCKS + PS_BLOCKS) {
        // fp16 prescale of x (independent of edges)
        int i = (b - DEG_BLOCKS) * 256 + t;
        if (i >= Nn * (Dd / 4)) return;
        int c4 = i & 31;
        int n = i >> 5;
        float4 v = __ldg(reinterpret_cast<const float4*>(x + (size_t)n * Dd) + c4);
        __half2 q0 = __floats2half2_rn(v.x, v.y);
        __half2 q1 = __floats2half2_rn(v.z, v.w);
        uint2 w;
        w.x = *reinterpret_cast<unsigned*>(&q0);
        w.y = *reinterpret_cast<unsigned*>(&q1);
        *reinterpret_cast<uint2*>(g_xh + (size_t)n * Dd + c4 * 4) = w;
    } else if (b < DEG_BLOCKS + PS_BLOCKS + P1_BLOCKS) {
        int idx = (b - DEG_BLOCKS - PS_BLOCKS) * 256 + t;
        if (idx >= Rr * Dd * OUTD) return;
        int r = idx / (Dd * OUTD);
        int rem = idx % (Dd * OUTD);
        int i = rem / OUTD, j = rem % OUTD;
        const float* wrow = W2 + ((size_t)r * Dd + i) * Dd;
        float s = 0.f;
#pragma unroll 8
        for (int k = 0; k < Dd; ++k) s += wrow[k] * Wlin[k * OUTD + j];
        g_G[idx] = BETA2c * s + (1.f - BETA2c) * Wlin[rem];
    } else {
        int idx = (b - DEG_BLOCKS - PS_BLOCKS - P1_BLOCKS) * 256 + t;
        if (idx >= Rr * Dd * Dd) return;
        int ij = idx % (Dd * Dd);
        int i = ij >> 7, j = ij & 127;
        float v = BETA1c * W1[idx] + ((i == j) ? (1.f - BETA1c) : 0.f);
        g_W1h[idx] = __float2half(v);
    }
}

// ---------------- launch B: row starts + dinv + prep2 --------------------------
#define RS_XBLOCKS ((Nn + 255) / 256)                        // 196
#define RS_BLOCKS  (RS_XBLOCKS * Rr)                         // 588
#define P2_BLOCKS  ((Dd * OUTD + 255) / 256)                 // 32
__global__ void k_rowstart_prep(const float* __restrict__ b2, const float* __restrict__ Wlin,
                                const float* __restrict__ blin) {
    int b = blockIdx.x;
    int t = threadIdx.x;
    if (b < RS_BLOCKS) {
        int r = b / RS_XBLOCKS;
        int n = (b % RS_XBLOCKS) * 256 + t;
        int lane = t & 31;
        int d = (n < Nn) ? g_deg_in[r * Nn + n] : 0;
        int incl = d;
#pragma unroll
        for (int o = 1; o < 32; o <<= 1) {
            int v = __shfl_up_sync(0xffffffffu, incl, o);
            if (lane >= o) incl += v;
        }
        int total = __shfl_sync(0xffffffffu, incl, 31);
        int base = 0;
        if (lane == 31) base = atomicAdd(&g_cursor[r], total);
        base = __shfl_sync(0xffffffffu, base, 31);
        if (n < Nn) {
            int start = r * Ee + base + incl - d;
            g_rowdeg [r * Nn + n] = make_int2(start, d);
            g_fillcur[r * Nn + n] = start;
            int di = d < 1 ? 1 : d;
            g_dinv_in[r * Nn + n] = rsqrtf((float)di);
            int doo = g_deg_out[r * Nn + n]; if (doo < 1) doo = 1;
            g_dinv_out[r * Nn + n] = rsqrtf((float)doo);
        }
    } else {
        int idx = (b - RS_BLOCKS) * 256 + t;
        if (idx < Dd * OUTD) {
            float v0 = g_G[idx], v1 = g_G[Dd * OUTD + idx], v2 = g_G[2 * Dd * OUTD + idx];
            g_Gxh[idx] = __float2half((ALPHAc / 3.f) * (v0 + v1 + v2));
            const float sc = (1.f - ALPHAc) / 3.f;
            g_Gh[idx]                 = __float2half(v0 * sc);
            g_Gh[Dd * OUTD + idx]     = __float2half(v1 * sc);
            g_Gh[2 * Dd * OUTD + idx] = __float2half(v2 * sc);
        }
        if (idx < OUTD) {
            float cc = blin[idx];
            for (int k = 0; k < Dd; ++k)
                cc += (b2[k] + b2[Dd + k] + b2[2 * Dd + k]) * (1.f / 3.f) * Wlin[k * OUTD + idx];
            g_c[idx] = cc;
        }
    }
}

// ---------------- launch C: CSR fill (packed scale) + counter re-zero ----------
#define CF_BLOCKS  ((Rr * Ee + 255) / 256)                   // 9375
#define ZB_BLOCKS  ((2 * Rr * Nn / 4 + 255) / 256 + 1)       // zero deg arrays (int4) + cursor
__global__ void k_csrfill_zero(const int* __restrict__ src, const int* __restrict__ dst) {
    int b = blockIdx.x;
    int t = threadIdx.x;
    if (b < CF_BLOCKS) {
        int i = b * 256 + t;
        if (i >= Rr * Ee) return;
        int r = i / Ee;
        int s = src[i];
        __half sh = __float2half(__ldg(g_dinv_out + r * Nn + s));
        unsigned entry = (unsigned)s |
                         ((unsigned)__half_as_ushort(sh) << 16);
        int pos = atomicAdd(&g_fillcur[r * Nn + dst[i]], 1);
        g_col[pos] = entry;
    } else {
        // re-zero degree counters + cursors for the next call (deg arrays are
        // fully consumed by rowstart_prep, which ran in the previous launch)
        int i = (b - CF_BLOCKS) * 256 + t;
        int4 z = make_int4(0, 0, 0, 0);
        if (i < Rr * Nn / 4) {
            reinterpret_cast<int4*>(g_deg_out)[i] = z;
            reinterpret_cast<int4*>(g_deg_in)[i]  = z;
        }
        if (i < Rr) g_cursor[i] = 0;
    }
}

// ---------------- fp16 helpers --------------------------------------------------
__device__ __forceinline__ void acc_h4(float4& acc, uint2 u) {
    __half2 a = *reinterpret_cast<__half2*>(&u.x);
    __half2 b = *reinterpret_cast<__half2*>(&u.y);
    float2 fa = __half22float2(a), fb = __half22float2(b);
    acc.x += fa.x; acc.y += fa.y; acc.z += fb.x; acc.w += fb.y;
}

// accumulate 8 halfs (uint4), scaled by s, into two float4
__device__ __forceinline__ void acc_h8s(float4& a0, float4& a1, uint4 u, float s) {
    __half2 h0 = *reinterpret_cast<__half2*>(&u.x);
    __half2 h1 = *reinterpret_cast<__half2*>(&u.y);
    __half2 h2 = *reinterpret_cast<__half2*>(&u.z);
    __half2 h3 = *reinterpret_cast<__half2*>(&u.w);
    float2 f0 = __half22float2(h0), f1 = __half22float2(h1);
    float2 f2 = __half22float2(h2), f3 = __half22float2(h3);
    a0.x += s * f0.x; a0.y += s * f0.y; a0.z += s * f1.x; a0.w += s * f1.y;
    a1.x += s * f2.x; a1.y += s * f2.y; a1.z += s * f3.x; a1.w += s * f3.y;
}

// accumulate 8 halfs (uint4, unscaled) into two float4
__device__ __forceinline__ void acc_h8(float4& a0, float4& a1, uint4 u) {
    acc_h4(a0, make_uint2(u.x, u.y));
    acc_h4(a1, make_uint2(u.z, u.w));
}

// pack 8 floats (scaled) -> 8 halfs (16B)
__device__ __forceinline__ uint4 pack_half8s(const float* v, float s) {
    __half2 p0 = __floats2half2_rn(v[0] * s, v[1] * s);
    __half2 p1 = __floats2half2_rn(v[2] * s, v[3] * s);
    __half2 p2 = __floats2half2_rn(v[4] * s, v[5] * s);
    __half2 p3 = __floats2half2_rn(v[6] * s, v[7] * s);
    uint4 u;
    u.x = *reinterpret_cast<unsigned*>(&p0);
    u.y = *reinterpret_cast<unsigned*>(&p1);
    u.z = *reinterpret_cast<unsigned*>(&p2);
    u.w = *reinterpret_cast<unsigned*>(&p3);
    return u;
}

// ---------------- gather (layer 1): 16-edge pipeline, MLP=8 -------------------
// aggh = (1-a)*dinv_in * sum_e(x[src]*dout[src]) + a*x[n]
__launch_bounds__(256)
__global__ void k_gather1() {
    int gw = (blockIdx.x * blockDim.x + threadIdx.x) >> 5;   // (r,n) index
    if (gw >= Rr * Nn) return;
    int lane = threadIdx.x & 31;
    int half = lane >> 4;          // 0: edge e, 1: edge e+1
    int sub  = lane & 15;          // halfs [sub*8, sub*8+8)
    int n = gw % Nn;

    int2 rd = __ldg(g_rowdeg + gw);
    int beg = rd.x, end = rd.x + rd.y;
    float4 a0 = make_float4(0.f, 0.f, 0.f, 0.f);
    float4 a1 = make_float4(0.f, 0.f, 0.f, 0.f);
    int e = beg;
#pragma unroll 1
    for (; e + 16 <= end; e += 16) {
        unsigned e0 = __ldg(g_col + e + 0  + half);
        unsigned e1 = __ldg(g_col + e + 2  + half);
        unsigned e2 = __ldg(g_col + e + 4  + half);
        unsigned e3 = __ldg(g_col + e + 6  + half);
        unsigned e4 = __ldg(g_col + e + 8  + half);
        unsigned e5 = __ldg(g_col + e + 10 + half);
        unsigned e6 = __ldg(g_col + e + 12 + half);
        unsigned e7 = __ldg(g_col + e + 14 + half);
        uint4 u0 = __ldg(reinterpret_cast<const uint4*>(g_xh + (size_t)(e0 & 0xffffu) * Dd) + sub);
        uint4 u1 = __ldg(reinterpret_cast<const uint4*>(g_xh + (size_t)(e1 & 0xffffu) * Dd) + sub);
        uint4 u2 = __ldg(reinterpret_cast<const uint4*>(g_xh + (size_t)(e2 & 0xffffu) * Dd) + sub);
        uint4 u3 = __ldg(reinterpret_cast<const uint4*>(g_xh + (size_t)(e3 & 0xffffu) * Dd) + sub);
        uint4 u4 = __ldg(reinterpret_cast<const uint4*>(g_xh + (size_t)(e4 & 0xffffu) * Dd) + sub);
        uint4 u5 = __ldg(reinterpret_cast<const uint4*>(g_xh + (size_t)(e5 & 0xffffu) * Dd) + sub);
        uint4 u6 = __ldg(reinterpret_cast<const uint4*>(g_xh + (size_t)(e6 & 0xffffu) * Dd) + sub);
        uint4 u7 = __ldg(reinterpret_cast<const uint4*>(g_xh + (size_t)(e7 & 0xffffu) * Dd) + sub);
        acc_h8s(a0, a1, u0, __half2float(__ushort_as_half((unsigned short)(e0 >> 16))));
        acc_h8s(a0, a1, u1, __half2float(__ushort_as_half((unsigned short)(e1 >> 16))));
        acc_h8s(a0, a1, u2, __half2float(__ushort_as_half((unsigned short)(e2 >> 16))));
        acc_h8s(a0, a1, u3, __half2float(__ushort_as_half((unsigned short)(e3 >> 16))));
        acc_h8s(a0, a1, u4, __half2float(__ushort_as_half((unsigned short)(e4 >> 16))));
        acc_h8s(a0, a1, u5, __half2float(__ushort_as_half((unsigned short)(e5 >> 16))));
        acc_h8s(a0, a1, u6, __half2float(__ushort_as_half((unsigned short)(e6 >> 16))));
        acc_h8s(a0, a1, u7, __half2float(__ushort_as_half((unsigned short)(e7 >> 16))));
    }
#pragma unroll 1
    for (; e + 8 <= end; e += 8) {
        unsigned e0 = __ldg(g_col + e + 0 + half);
        unsigned e1 = __ldg(g_col + e + 2 + half);
        unsigned e2 = __ldg(g_col + e + 4 + half);
        unsigned e3 = __ldg(g_col + e + 6 + half);
        uint4 u0 = __ldg(reinterpret_cast<const uint4*>(g_xh + (size_t)(e0 & 0xffffu) * Dd) + sub);
        uint4 u1 = __ldg(reinterpret_cast<const uint4*>(g_xh + (size_t)(e1 & 0xffffu) * Dd) + sub);
        uint4 u2 = __ldg(reinterpret_cast<const uint4*>(g_xh + (size_t)(e2 & 0xffffu) * Dd) + sub);
        uint4 u3 = __ldg(reinterpret_cast<const uint4*>(g_xh + (size_t)(e3 & 0xffffu) * Dd) + sub);
        acc_h8s(a0, a1, u0, __half2float(__ushort_as_half((unsigned short)(e0 >> 16))));
        acc_h8s(a0, a1, u1, __half2float(__ushort_as_half((unsigned short)(e1 >> 16))));
        acc_h8s(a0, a1, u2, __half2float(__ushort_as_half((unsigned short)(e2 >> 16))));
        acc_h8s(a0, a1, u3, __half2float(__ushort_as_half((unsigned short)(e3 >> 16))));
    }
#pragma unroll 1
    for (; e < end; e += 2) {
        if (e + half < end) {
            unsigned e0 = __ldg(g_col + e + half);
            uint4 u0 = __ldg(reinterpret_cast<const uint4*>(g_xh + (size_t)(e0 & 0xffffu) * Dd) + sub);
            acc_h8s(a0, a1, u0, __half2float(__ushort_as_half((unsigned short)(e0 >> 16))));
        }
    }
    // merge the two half-warps (full-warp shfl before any divergence)
    a0.x += __shfl_xor_sync(0xffffffffu, a0.x, 16);
    a0.y += __shfl_xor_sync(0xffffffffu, a0.y, 16);
    a0.z += __shfl_xor_sync(0xffffffffu, a0.z, 16);
    a0.w += __shfl_xor_sync(0xffffffffu, a0.w, 16);
    a1.x += __shfl_xor_sync(0xffffffffu, a1.x, 16);
    a1.y += __shfl_xor_sync(0xffffffffu, a1.y, 16);
    a1.z += __shfl_xor_sync(0xffffffffu, a1.z, 16);
    a1.w += __shfl_xor_sync(0xffffffffu, a1.w, 16);

    if (half == 0) {
        float sc = __ldg(g_dinv_in + gw) * (1.f - ALPHAc);
        uint4 xv = __ldg(reinterpret_cast<const uint4*>(g_xh + (size_t)n * Dd) + sub);
        float4 x0 = make_float4(0.f, 0.f, 0.f, 0.f);
        float4 x1 = make_float4(0.f, 0.f, 0.f, 0.f);
        acc_h8(x0, x1, xv);
        float v[8];
        v[0] = a0.x * sc + ALPHAc * x0.x;
        v[1] = a0.y * sc + ALPHAc * x0.y;
        v[2] = a0.z * sc + ALPHAc * x0.z;
        v[3] = a0.w * sc + ALPHAc * x0.w;
        v[4] = a1.x * sc + ALPHAc * x1.x;
        v[5] = a1.y * sc + ALPHAc * x1.y;
        v[6] = a1.z * sc + ALPHAc * x1.z;
        v[7] = a1.w * sc + ALPHAc * x1.w;
        uint4 u = pack_half8s(v, 1.f);
        *(reinterpret_cast<uint4*>(g_aggh + (size_t)gw * Dd) + sub) = u;
    }
}

// copy a 64x128 fp16 tile global -> smem (stride 136), coalesced uint4
__device__ __forceinline__ void stage_tile(__half* Ah, const __half* __restrict__ Ab,
                                           int tid) {
#pragma unroll
    for (int it = 0; it < 4; ++it) {
        int idx = it * 256 + tid;            // 1024 uint4 total
        int row = idx >> 4, c8 = idx & 15;
        uint4 u = __ldg(reinterpret_cast<const uint4*>(Ab + (size_t)row * Dd) + c8);
        *reinterpret_cast<uint4*>(Ah + row * 136 + c8 * 8) = u;
    }
}

// ---------------- layer-1 GEMM + fused z-projection + x@Gx slice --------------
#define GB1_BLOCKS ((Nn + 63) / 64)                          // 782
#define XG_BLOCKS  ((Nn + 63) / 64)                          // 782
__launch_bounds__(256)
__global__ void k_gemm1(const float* __restrict__ b1, const float* __restrict__ x,
                        float* __restrict__ out) {
    __shared__ __align__(16) __half Ah[64 * 136];   // 17408 B
    __shared__ __align__(16) float  Cs[64 * 132];   // 33792 B
    int tid = threadIdx.x;
    int warp = tid >> 5;
    int ty = tid >> 4, tx = tid & 15;
    int wr = warp >> 1, wc = warp & 1;

    if (blockIdx.x >= GB1_BLOCKS) {
        // ---- light path: out = x @ Gx + c
        int n0 = (blockIdx.x - GB1_BLOCKS) << 6;
#pragma unroll
        for (int it = 0; it < 8; ++it) {
            int idx = it * 256 + tid;              // 2048
            int row = idx >> 5, c4 = idx & 31;
            int n = n0 + row;
            float4 v = (n < Nn)
                ? __ldg(reinterpret_cast<const float4*>(x + (size_t)n * Dd) + c4)
                : make_float4(0.f, 0.f, 0.f, 0.f);
            __half2 p0 = __floats2half2_rn(v.x, v.y);
            __half2 p1 = __floats2half2_rn(v.z, v.w);
            uint2 u;
            u.x = *reinterpret_cast<unsigned*>(&p0);
            u.y = *reinterpret_cast<unsigned*>(&p1);
            *reinterpret_cast<uint2*>(Ah + row * 136 + c4 * 4) = u;
        }
        __syncthreads();
        wmma::fragment<wmma::accumulator, 16, 16, 16, float> acc[2];
#pragma unroll
        for (int f = 0; f < 2; ++f) wmma::fill_fragment(acc[f], 0.f);
#pragma unroll
        for (int k = 0; k < 8; ++k) {
            wmma::fragment<wmma::matrix_a, 16, 16, 16, __half, wmma::row_major> af;
            wmma::load_matrix_sync(af, Ah + (wr * 16) * 136 + k * 16, 136);
#pragma unroll
            for (int f = 0; f < 2; ++f) {
                wmma::fragment<wmma::matrix_b, 16, 16, 16, __half, wmma::row_major> bf;
                wmma::load_matrix_sync(bf, g_Gxh + (k * 16) * OUTD + wc * 32 + f * 16, OUTD);
                wmma::mma_sync(acc[f], af, bf, acc[f]);
            }
        }
#pragma unroll
        for (int f = 0; f < 2; ++f)
            wmma::store_matrix_sync(Cs + (wr * 16) * 68 + wc * 32 + f * 16, acc[f], 68,
                                    wmma::mem_row_major);
        __syncthreads();
#pragma unroll
        for (int it = 0; it < 8; ++it) {
            int idx = it * 256 + tid;
            int row = idx >> 5, cp = idx & 31;
            int n = n0 + row;
            if (n < Nn) {
                float2 p;
                p.x = Cs[row * 68 + cp * 2]     + g_c[cp * 2];
                p.y = Cs[row * 68 + cp * 2 + 1] + g_c[cp * 2 + 1];
                *(reinterpret_cast<float2*>(out + (size_t)n * OUTD) + cp) = p;
            }
        }
        return;
    }

    // ---- heavy path: h1 tile via 3 relation GEMMs, then z_r projection
    int n0 = blockIdx.x << 6;
    float hacc[4][8];
#pragma unroll
    for (int i = 0; i < 4; ++i)
#pragma unroll
        for (int j = 0; j < 8; ++j) hacc[i][j] = 0.f;

    for (int r = 0; r < Rr; ++r) {
        if (r > 0) __syncthreads();
        stage_tile(Ah, g_aggh + ((size_t)r * Nn + n0) * Dd, tid);
        __syncthreads();

        wmma::fragment<wmma::accumulator, 16, 16, 16, float> acc[4];
#pragma unroll
        for (int f = 0; f < 4; ++f) wmma::fill_fragment(acc[f], 0.f);
        const __half* Bg = g_W1h + (size_t)r * Dd * Dd;
#pragma unroll
        for (int k = 0; k < 8; ++k) {
            wmma::fragment<wmma::matrix_a, 16, 16, 16, __half, wmma::row_major> af;
            wmma::load_matrix_sync(af, Ah + (wr * 16) * 136 + k * 16, 136);
#pragma unroll
            for (int f = 0; f < 4; ++f) {
                wmma::fragment<wmma::matrix_b, 16, 16, 16, __half, wmma::row_major> bf;
                wmma::load_matrix_sync(bf, Bg + (k * 16) * Dd + wc * 64 + f * 16, Dd);
                wmma::mma_sync(acc[f], af, bf, acc[f]);
            }
        }
#pragma unroll
        for (int f = 0; f < 4; ++f)
            wmma::store_matrix_sync(Cs + (wr * 16) * 132 + wc * 64 + f * 16, acc[f], 132,
                                    wmma::mem_row_major);
        __syncthreads();

#pragma unroll
        for (int i = 0; i < 4; ++i) {
            int row = ty * 4 + i;
#pragma unroll
            for (int j = 0; j < 8; ++j) {
                int col = tx * 8 + j;
                float v = Cs[row * 132 + col] + b1[r * Dd + col];
                v = v >= 0.f ? v : SLOPEc * v;
                hacc[i][j] += v * (1.f / 3.f);
            }
        }
    }

    // z_r = (h1 * dinv_out_r) @ G_r straight from registers
    for (int r = 0; r < Rr; ++r) {
        __syncthreads();
#pragma unroll
        for (int i = 0; i < 4; ++i) {
            int row = ty * 4 + i;
            int n = n0 + row;
            float s = (n < Nn) ? __ldg(g_dinv_out + r * Nn + n) : 0.f;
            uint4 u = pack_half8s(hacc[i], s);
            *reinterpret_cast<uint4*>(Ah + row * 136 + tx * 8) = u;
        }
        __syncthreads();

        wmma::fragment<wmma::accumulator, 16, 16, 16, float> acc2[2];
#pragma unroll
        for (int f = 0; f < 2; ++f) wmma::fill_fragment(acc2[f], 0.f);
        const __half* Bb = g_Gh + (size_t)r * Dd * OUTD;
#pragma unroll
        for (int k = 0; k < 8; ++k) {
            wmma::fragment<wmma::matrix_a, 16, 16, 16, __half, wmma::row_major> af;
            wmma::load_matrix_sync(af, Ah + (wr * 16) * 136 + k * 16, 136);
#pragma unroll
            for (int f = 0; f < 2; ++f) {
                wmma::fragment<wmma::matrix_b, 16, 16, 16, __half, wmma::row_major> bf;
                wmma::load_matrix_sync(bf, Bb + (k * 16) * OUTD + wc * 32 + f * 16, OUTD);
                wmma::mma_sync(acc2[f], af, bf, acc2[f]);
            }
        }
#pragma unroll
        for (int f = 0; f < 2; ++f)
            wmma::store_matrix_sync(Cs + (wr * 16) * 68 + wc * 32 + f * 16, acc2[f], 68,
                                    wmma::mem_row_major);
        __syncthreads();

#pragma unroll
        for (int it = 0; it < 8; ++it) {
            int idx = it * 256 + tid;        // 2048
            int row = idx >> 5, cp = idx & 31;
            int n = n0 + row;
            if (n < Nn) {
                __half2 p = __floats2half2_rn(Cs[row * 68 + cp * 2], Cs[row * 68 + cp * 2 + 1]);
                *(reinterpret_cast<unsigned*>(g_z + ((size_t)r * Nn + n) * OUTD) + cp) =
                    *reinterpret_cast<unsigned*>(&p);
            }
        }
    }
}

// ---------------- combine: 16-edge pipeline, red.v4 into out -------------------
__launch_bounds__(256)
__global__ void k_combine(float* __restrict__ out) {
    int gw = (blockIdx.x * blockDim.x + threadIdx.x) >> 5;   // (r,n)
    if (gw >= Rr * Nn) return;
    int lane = threadIdx.x & 31;
    int half = lane >> 4;          // 0: edge e, 1: edge e+1
    int sub  = lane & 15;          // cols [sub*4, sub*4+4)
    int n = gw % Nn;
    const __half* zb = g_z + (size_t)(gw / Nn) * Nn * OUTD;

    int2 rd = __ldg(g_rowdeg + gw);
    int beg = rd.x, end = rd.x + rd.y;
    float4 acc = make_float4(0.f, 0.f, 0.f, 0.f);
    int e = beg;
#pragma unroll 1
    for (; e + 16 <= end; e += 16) {
        unsigned e0 = __ldg(g_col + e + 0  + half);
        unsigned e1 = __ldg(g_col + e + 2  + half);
        unsigned e2 = __ldg(g_col + e + 4  + half);
        unsigned e3 = __ldg(g_col + e + 6  + half);
        unsigned e4 = __ldg(g_col + e + 8  + half);
        unsigned e5 = __ldg(g_col + e + 10 + half);
        unsigned e6 = __ldg(g_col + e + 12 + half);
        unsigned e7 = __ldg(g_col + e + 14 + half);
        uint2 u0 = __ldg(reinterpret_cast<const uint2*>(zb + (size_t)(e0 & 0xffffu) * OUTD) + sub);
        uint2 u1 = __ldg(reinterpret_cast<const uint2*>(zb + (size_t)(e1 & 0xffffu) * OUTD) + sub);
        uint2 u2 = __ldg(reinterpret_cast<const uint2*>(zb + (size_t)(e2 & 0xffffu) * OUTD) + sub);
        uint2 u3 = __ldg(reinterpret_cast<const uint2*>(zb + (size_t)(e3 & 0xffffu) * OUTD) + sub);
        uint2 u4 = __ldg(reinterpret_cast<const uint2*>(zb + (size_t)(e4 & 0xffffu) * OUTD) + sub);
        uint2 u5 = __ldg(reinterpret_cast<const uint2*>(zb + (size_t)(e5 & 0xffffu) * OUTD) + sub);
        uint2 u6 = __ldg(reinterpret_cast<const uint2*>(zb + (size_t)(e6 & 0xffffu) * OUTD) + sub);
        uint2 u7 = __ldg(reinterpret_cast<const uint2*>(zb + (size_t)(e7 & 0xffffu) * OUTD) + sub);
        acc_h4(acc, u0); acc_h4(acc, u1); acc_h4(acc, u2); acc_h4(acc, u3);
        acc_h4(acc, u4); acc_h4(acc, u5); acc_h4(acc, u6); acc_h4(acc, u7);
    }
#pragma unroll 1
    for (; e + 8 <= end; e += 8) {
        unsigned e0 = __ldg(g_col + e + 0 + half);
        unsigned e1 = __ldg(g_col + e + 2 + half);
        unsigned e2 = __ldg(g_col + e + 4 + half);
        unsigned e3 = __ldg(g_col + e + 6 + half);
        uint2 u0 = __ldg(reinterpret_cast<const uint2*>(zb + (size_t)(e0 & 0xffffu) * OUTD) + sub);
        uint2 u1 = __ldg(reinterpret_cast<const uint2*>(zb + (size_t)(e1 & 0xffffu) * OUTD) + sub);
        uint2 u2 = __ldg(reinterpret_cast<const uint2*>(zb + (size_t)(e2 & 0xffffu) * OUTD) + sub);
        uint2 u3 = __ldg(reinterpret_cast<const uint2*>(zb + (size_t)(e3 & 0xffffu) * OUTD) + sub);
        acc_h4(acc, u0); acc_h4(acc, u1); acc_h4(acc, u2); acc_h4(acc, u3);
    }
#pragma unroll 1
    for (; e < end; e += 2) {
        if (e + half < end) {
            unsigned e0 = __ldg(g_col + e + half);
            uint2 u0 = __ldg(reinterpret_cast<const uint2*>(zb + (size_t)(e0 & 0xffffu) * OUTD) + sub);
            acc_h4(acc, u0);
        }
    }
    // merge half-warps (full-warp shfl before divergence)
    acc.x += __shfl_xor_sync(0xffffffffu, acc.x, 16);
    acc.y += __shfl_xor_sync(0xffffffffu, acc.y, 16);
    acc.z += __shfl_xor_sync(0xffffffffu, acc.z, 16);
    acc.w += __shfl_xor_sync(0xffffffffu, acc.w, 16);

    if (half == 0) {
        float di = __ldg(g_dinv_in + gw);
        float v0 = acc.x * di, v1 = acc.y * di, v2 = acc.z * di, v3 = acc.w * di;
        float* p = out + (size_t)n * OUTD + sub * 4;
        asm volatile("red.global.add.v4.f32 [%0], {%1,%2,%3,%4};"
                     :: "l"(p), "f"(v0), "f"(v1), "f"(v2), "f"(v3) : "memory");
    }
}

// ---------------- launch ------------------------------------------------------
extern "C" void kernel_launch(void* const* d_in, const int* in_sizes, int n_in,
                              void* d_out, int out_size) {
    const float* x    = (const float*)d_in[0];
    const int*   src  = (const int*)  d_in[1];
    const int*   dst  = (const int*)  d_in[2];
    const float* W1   = (const float*)d_in[3];
    const float* b1   = (const float*)d_in[4];
    const float* W2   = (const float*)d_in[5];
    const float* b2   = (const float*)d_in[6];
    const float* Wlin = (const float*)d_in[7];
    const float* blin = (const float*)d_in[8];
    float* out = (float*)d_out;

    k_degree_prep<<<DEG_BLOCKS + PS_BLOCKS + P1_BLOCKS + PW1_BLOCKS, 256>>>(
        src, dst, W2, Wlin, W1, x);
    k_rowstart_prep<<<RS_BLOCKS + P2_BLOCKS, 256>>>(b2, Wlin, blin);
    k_csrfill_zero<<<CF_BLOCKS + ZB_BLOCKS, 256>>>(src, dst);

    const int gather_blocks = (Rr * Nn * 32 + 255) / 256;   // one warp per (r,n)
    k_gather1<<<gather_blocks, 256>>>();
    k_gemm1<<<GB1_BLOCKS + XG_BLOCKS, 256>>>(b1, x, out);
    k_combine<<<gather_blocks, 256>>>(out);
}